// round 15
// baseline (speedup 1.0000x reference)
#include <cuda_runtime.h>
#include <cuda_bf16.h>
#include <math.h>
#include <stdint.h>

typedef __nv_bfloat16 bf16;

#define N_ATOMS 65536
#define N_BONDS 98304
#define N_MOLS  4096
#define D_IN    128
#define D       256

// ---------------- scratch (device globals; no allocation allowed) ----------------
__device__ bf16 g_he_hi [2][(size_t)N_BONDS * D];
__device__ bf16 g_he_lo [2][(size_t)N_BONDS * D];
__device__ bf16 g_he0_hi[(size_t)N_BONDS * D];
__device__ bf16 g_he0_lo[(size_t)N_BONDS * D];
__device__ bf16 g_hv_hi [2][(size_t)N_ATOMS * D];
__device__ bf16 g_hv_lo [2][(size_t)N_ATOMS * D];
__device__ bf16 g_hv0_hi[(size_t)N_ATOMS * D];
__device__ bf16 g_hv0_lo[(size_t)N_ATOMS * D];
__device__ float g_ebv_f [(size_t)N_ATOMS * D];
__device__ bf16 g_hu_hi [2][(size_t)N_MOLS * D];
__device__ bf16 g_hu_lo [2][(size_t)N_MOLS * D];
__device__ bf16 g_hu0_hi[(size_t)N_MOLS * D];
__device__ bf16 g_hu0_lo[(size_t)N_MOLS * D];
__device__ bf16 g_ebar_hi[(size_t)N_MOLS * D];
__device__ bf16 g_ebar_lo[(size_t)N_MOLS * D];
__device__ bf16 g_vbar_hi[(size_t)N_MOLS * D];
__device__ bf16 g_vbar_lo[(size_t)N_MOLS * D];
__device__ bf16 g_mm_hi [(size_t)N_MOLS * D_IN];
__device__ bf16 g_mm_lo [(size_t)N_MOLS * D_IN];
__device__ bf16 g_at_hi [(size_t)N_ATOMS * D_IN];
__device__ bf16 g_at_lo [(size_t)N_ATOMS * D_IN];
__device__ bf16 g_we_hi [(size_t)D * 5 * D];
__device__ bf16 g_we_lo [(size_t)D * 5 * D];
__device__ bf16 g_wv_hi [(size_t)D * 4 * D];
__device__ bf16 g_wv_lo [(size_t)D * 4 * D];
__device__ bf16 g_wu_hi [(size_t)D * 4 * D];
__device__ bf16 g_wu_lo [(size_t)D * 4 * D];
__device__ bf16 g_wfv_hi[(size_t)D * D_IN];
__device__ bf16 g_wfv_lo[(size_t)D * D_IN];
__device__ bf16 g_wfu_hi[(size_t)D * D_IN];
__device__ bf16 g_wfu_lo[(size_t)D * D_IN];
// precomputed fp32 epilogue-add terms
__device__ float g_E0 [(size_t)N_BONDS * D];
__device__ float g_V0t[(size_t)N_ATOMS * D];
__device__ float g_U0 [(size_t)N_MOLS * D];
__device__ float g_Ue [(size_t)N_MOLS * D];
__device__ float g_Uv [(size_t)N_MOLS * D];
__device__ float g_Vs [(size_t)N_ATOMS * D];
__device__ float g_Vd [(size_t)N_ATOMS * D];
__device__ int  g_boff[N_MOLS + 1];
__device__ int  g_aoff[N_MOLS + 1];

// ---------------- helpers ----------------
__device__ __forceinline__ uint32_t smem_u32(const void* p) {
    uint32_t a;
    asm("{ .reg .u64 t; cvta.to.shared.u64 t, %1; cvt.u32.u64 %0, t; }" : "=r"(a) : "l"(p));
    return a;
}
__device__ __forceinline__ void cp16(uint32_t dst, const void* src) {
    asm volatile("cp.async.cg.shared.global [%0], [%1], 16;" :: "r"(dst), "l"(src) : "memory");
}
#define CP_COMMIT()  asm volatile("cp.async.commit_group;" ::: "memory")
#define CP_WAIT0()   asm volatile("cp.async.wait_group 0;" ::: "memory")

__device__ __forceinline__ void ldsm4(uint32_t* r, uint32_t addr) {
    asm volatile("ldmatrix.sync.aligned.m8n8.x4.shared.b16 {%0,%1,%2,%3}, [%4];"
        : "=r"(r[0]), "=r"(r[1]), "=r"(r[2]), "=r"(r[3]) : "r"(addr));
}
__device__ __forceinline__ void mma_bf16(float* c, const uint32_t* a, const uint32_t* b) {
    asm volatile(
        "mma.sync.aligned.m16n8k16.row.col.f32.bf16.bf16.f32 "
        "{%0,%1,%2,%3}, {%4,%5,%6,%7}, {%8,%9}, {%0,%1,%2,%3};"
        : "+f"(c[0]), "+f"(c[1]), "+f"(c[2]), "+f"(c[3])
        : "r"(a[0]), "r"(a[1]), "r"(a[2]), "r"(a[3]), "r"(b[0]), "r"(b[1]));
}
__device__ __forceinline__ void red4(float* p, float4 v) {
    asm volatile("red.global.add.v4.f32 [%0], {%1,%2,%3,%4};"
        :: "l"(p), "f"(v.x), "f"(v.y), "f"(v.z), "f"(v.w) : "memory");
}
__device__ __forceinline__ void split1(float v, bf16& h, bf16& l) {
    h = __float2bfloat16(v);
    l = __float2bfloat16(v - __bfloat162float(h));
}
// packed split: 2 cvt + shl/and + 2 sub per PAIR of values
__device__ __forceinline__ void split2(float v0, float v1, uint32_t& h2, uint32_t& l2) {
    asm("cvt.rn.bf16x2.f32 %0, %1, %2;" : "=r"(h2) : "f"(v1), "f"(v0));
    const float f0 = __uint_as_float(h2 << 16);
    const float f1 = __uint_as_float(h2 & 0xffff0000u);
    const float l0 = v0 - f0;
    const float l1 = v1 - f1;
    asm("cvt.rn.bf16x2.f32 %0, %1, %2;" : "=r"(l2) : "f"(l1), "f"(l0));
}
__device__ __forceinline__ float tanh_approx(float x) {
    float y;
    asm("tanh.approx.f32 %0, %1;" : "=f"(y) : "f"(x));
    return y;
}
__device__ __forceinline__ float tanh_precise(float x) {
    const float e = __expf(2.0f * x);
    return 1.0f - __fdividef(2.0f, e + 1.0f);
}

// ---------------- fused multi-source bf16x3 GEMM (+adds, +scatter, +tanh) ---------
struct Srcs {
    const void* Ahi[4];
    const void* Alo[4];
    const int*  idx[4];
    int         wblk[4];
    int         isf32[4];
};
struct Adds {
    const float* direct;
    const float* gat[3];
    const int*   gidx[3];
};
struct Scat {
    float*     buf;
    const int* i0;
    const int* i1;
};

#define TILE_B   10240
#define SM_A     0
#define SM_B     40960
#define SMEM_BYTES 81920

__global__ void __launch_bounds__(256, 2)
k_mma(Srcs srcs, int ksrc, int cshift, int n_chunks,
      const bf16* __restrict__ Whi, const bf16* __restrict__ Wlo, int kstride,
      const bf16* __restrict__ Whi2, const bf16* __restrict__ Wlo2, int kstride2,
      Adds adds, Scat scat, int do_tanh,
      int ysplit, int wblk_alt,
      float* __restrict__ out_f32, float* __restrict__ out_alt,
      bf16* __restrict__ out_hi, bf16* __restrict__ out_lo)
{
    extern __shared__ char smc[];
    const uint32_t smu = smem_u32(smc);

    const int tid  = threadIdx.x;
    const int lane = tid & 31;
    const int w    = tid >> 5;
    const int wm   = w & 3;
    const int wn   = w >> 2;
    const int lr   = lane >> 2;
    const int lc   = lane & 3;

    const int n0 = blockIdx.x * 128;
    const int yb = blockIdx.y;
    const bool alt = (ysplit > 0) && (yb >= ysplit);
    const int m0 = (alt ? yb - ysplit : yb) * 128;

    const int cmask = (ksrc >> 5) - 1;

    const int r8 = lane & 7, j8 = lane >> 3;
    const uint32_t offA = (uint32_t)((r8 + (j8 & 1) * 8) * 80 + ((j8 >> 1) & 1) * 16)
                        + (uint32_t)(wm * 32) * 80u;
    const uint32_t offB = (uint32_t)(r8 * 80 + ((j8 >> 1) & 1) * 640 + (j8 & 1) * 16)
                        + (uint32_t)(wn * 64) * 80u;

    const int arow = tid >> 1;
    const int apl  = tid & 1;
    int cur_s = -1, is32 = 0, wcur = 0;
    const bf16*  aptr = nullptr;
    const float* a32  = nullptr;
    const bf16* wbase = alt ? (apl ? Wlo2 : Whi2) : (apl ? Wlo : Whi);
    const int   kstr  = alt ? kstride2 : kstride;

    auto load_chunk = [&](int c) {
        const int buf = c & 1;
        const int s = c >> cshift;
        if (s != cur_s) {
            cur_s = s;
            is32 = srcs.isf32[s];
            int gr = m0 + arow;
            const int* ix = srcs.idx[s];
            if (ix) gr = __ldg(ix + gr);
            if (is32) a32 = (const float*)srcs.Ahi[s] + (size_t)gr * ksrc;
            else aptr = (const bf16*)(apl ? srcs.Alo[s] : srcs.Ahi[s]) + (size_t)gr * ksrc;
            wcur = (s == 0 && alt) ? wblk_alt : srcs.wblk[s];
        }
        const uint32_t ad = smu + (uint32_t)(SM_A + apl * 2 * TILE_B + buf * TILE_B + arow * 80);
        if (is32) {
            const float* fs = a32 + ((c & cmask) << 5);
#pragma unroll
            for (int i = 0; i < 4; i++) {
                float4 x = __ldg((const float4*)(fs + i * 8));
                float4 y = __ldg((const float4*)(fs + i * 8 + 4));
                uint32_t h, l, r0, r1, r2, r3;
                split2(x.x, x.y, h, l); r0 = apl ? l : h;
                split2(x.z, x.w, h, l); r1 = apl ? l : h;
                split2(y.x, y.y, h, l); r2 = apl ? l : h;
                split2(y.z, y.w, h, l); r3 = apl ? l : h;
                asm volatile("st.shared.v4.b32 [%0], {%1,%2,%3,%4};"
                    :: "r"(ad + (uint32_t)(i * 16)), "r"(r0), "r"(r1), "r"(r2), "r"(r3)
                    : "memory");
            }
        } else {
            const bf16* as = aptr + ((c & cmask) << 5);
            cp16(ad,      as);
            cp16(ad + 16, as + 8);
            cp16(ad + 32, as + 16);
            cp16(ad + 48, as + 24);
        }
        const bf16* bs = wbase + (size_t)(n0 + arow) * kstr
                       + (wcur << 8) + ((c & cmask) << 5);
        const uint32_t bd = smu + (uint32_t)(SM_B + apl * 2 * TILE_B + buf * TILE_B + arow * 80);
        cp16(bd,      bs);
        cp16(bd + 16, bs + 8);
        cp16(bd + 32, bs + 16);
        cp16(bd + 48, bs + 24);
    };

    float acc[2][8][4];
#pragma unroll
    for (int mi = 0; mi < 2; mi++)
#pragma unroll
        for (int nj = 0; nj < 8; nj++)
#pragma unroll
            for (int q = 0; q < 4; q++) acc[mi][nj][q] = 0.f;

    load_chunk(0);
    CP_COMMIT();

    for (int c = 0; c < n_chunks; c++) {
        CP_WAIT0();
        __syncthreads();
        if (c + 1 < n_chunks) load_chunk(c + 1);
        CP_COMMIT();

        const int buf = c & 1;
        const uint32_t aH = smu + SM_A + (uint32_t)(buf * TILE_B);
        const uint32_t aL = aH + 2u * TILE_B;
        const uint32_t bH = smu + SM_B + (uint32_t)(buf * TILE_B);
        const uint32_t bL = bH + 2u * TILE_B;

#pragma unroll
        for (int ks = 0; ks < 2; ks++) {
            const uint32_t kb = (uint32_t)(ks * 32);
            uint32_t ah[2][4], al[2][4];
            ldsm4(ah[0], aH + offA + kb);
            ldsm4(ah[1], aH + offA + 1280u + kb);
            ldsm4(al[0], aL + offA + kb);
            ldsm4(al[1], aL + offA + 1280u + kb);
#pragma unroll
            for (int g = 0; g < 2; g++) {
                const uint32_t go = (uint32_t)(g * 2560);
                uint32_t bh[4][2], bl[4][2];
                ldsm4(&bh[0][0], bH + offB + go + kb);
                ldsm4(&bh[2][0], bH + offB + go + 1280u + kb);
                ldsm4(&bl[0][0], bL + offB + go + kb);
                ldsm4(&bl[2][0], bL + offB + go + 1280u + kb);
#pragma unroll
                for (int mi = 0; mi < 2; mi++)
#pragma unroll
                    for (int q = 0; q < 4; q++) {
                        float* acq = acc[mi][g * 4 + q];
                        mma_bf16(acq, ah[mi], bh[q]);
                        mma_bf16(acq, ah[mi], bl[q]);
                        mma_bf16(acq, al[mi], bh[q]);
                    }
            }
        }
        __syncthreads();
    }

    float* outf = alt ? out_alt : out_f32;

    // epilogue
#pragma unroll
    for (int mi = 0; mi < 2; mi++) {
        const int r0 = m0 + wm * 32 + mi * 16 + lr;
        const int r1 = r0 + 8;
        const float* dp0 = adds.direct ? adds.direct + (size_t)r0 * D : nullptr;
        const float* dp1 = adds.direct ? adds.direct + (size_t)r1 * D : nullptr;
        const float* gp[3][2];
#pragma unroll
        for (int t = 0; t < 3; t++) {
            if (adds.gat[t]) {
                gp[t][0] = adds.gat[t] + (size_t)__ldg(adds.gidx[t] + r0) * D;
                gp[t][1] = adds.gat[t] + (size_t)__ldg(adds.gidx[t] + r1) * D;
            } else {
                gp[t][0] = nullptr; gp[t][1] = nullptr;
            }
        }
        float *s00 = nullptr, *s01 = nullptr, *s10 = nullptr, *s11 = nullptr;
        if (scat.buf) {
            s00 = scat.buf + (size_t)__ldg(scat.i0 + r0) * D;
            s01 = scat.buf + (size_t)__ldg(scat.i0 + r1) * D;
            s10 = scat.buf + (size_t)__ldg(scat.i1 + r0) * D;
            s11 = scat.buf + (size_t)__ldg(scat.i1 + r1) * D;
        }
#pragma unroll
        for (int nj = 0; nj < 8; nj++) {
            const int col = n0 + wn * 64 + nj * 8 + lc * 2;
            float v0 = acc[mi][nj][0];
            float v1 = acc[mi][nj][1];
            float v2 = acc[mi][nj][2];
            float v3 = acc[mi][nj][3];
            if (dp0) {
                float2 t0 = *(const float2*)(dp0 + col);
                float2 t1 = *(const float2*)(dp1 + col);
                v0 += t0.x; v1 += t0.y; v2 += t1.x; v3 += t1.y;
            }
#pragma unroll
            for (int t = 0; t < 3; t++) {
                if (gp[t][0]) {
                    float2 t0 = *(const float2*)(gp[t][0] + col);
                    float2 t1 = *(const float2*)(gp[t][1] + col);
                    v0 += t0.x; v1 += t0.y; v2 += t1.x; v3 += t1.y;
                }
            }
            if (do_tanh == 1) {
                v0 = tanh_approx(v0); v1 = tanh_approx(v1);
                v2 = tanh_approx(v2); v3 = tanh_approx(v3);
            } else if (do_tanh == 2) {
                v0 = tanh_precise(v0); v1 = tanh_precise(v1);
                v2 = tanh_precise(v2); v3 = tanh_precise(v3);
            }
            if (s00) {
                // lane-pair butterfly: each thread ends up with 4 consecutive
                // columns of ONE row (even lc: r0; odd lc: r1), then 2×red4
                // replace 4×red2 (same bytes, half the atomic issue count).
                const float t0 = (lc & 1) ? v0 : v2;
                const float t1 = (lc & 1) ? v1 : v3;
                const float u0 = __shfl_xor_sync(0xffffffffu, t0, 1);
                const float u1 = __shfl_xor_sync(0xffffffffu, t1, 1);
                float4 q;
                float *b0, *b1;
                if (lc & 1) {
                    q = make_float4(u0, u1, v2, v3);
                    b0 = s01; b1 = s11;
                } else {
                    q = make_float4(v0, v1, u0, u1);
                    b0 = s00; b1 = s10;
                }
                const int c4 = n0 + wn * 64 + nj * 8 + ((lc & 2) << 1);
                red4(b0 + c4, q);
                red4(b1 + c4, q);
            }
            if (outf) {
                *(float2*)(outf + (size_t)r0 * D + col) = make_float2(v0, v1);
                *(float2*)(outf + (size_t)r1 * D + col) = make_float2(v2, v3);
            }
            if (out_hi) {
                uint32_t h01, l01, h23, l23;
                split2(v0, v1, h01, l01);
                split2(v2, v3, h23, l23);
                const size_t o0 = (size_t)r0 * D + col;
                const size_t o1 = (size_t)r1 * D + col;
                *(uint32_t*)(out_hi + o0) = h01;  *(uint32_t*)(out_lo + o0) = l01;
                *(uint32_t*)(out_hi + o1) = h23;  *(uint32_t*)(out_lo + o1) = l23;
            }
        }
    }
}

// ---------------- small kernels ----------------
__global__ void k_offsets2(const int* __restrict__ bids, const int* __restrict__ aids,
                           int* __restrict__ boff, int* __restrict__ aoff)
{
    int m = blockIdx.x * blockDim.x + threadIdx.x;
    if (m > N_MOLS) return;
    const int* ids = blockIdx.y ? aids : bids;
    const int n    = blockIdx.y ? N_ATOMS : N_BONDS;
    int* off       = blockIdx.y ? aoff : boff;
    int lo = 0, hi = n;
    while (lo < hi) {
        int mid = (lo + hi) >> 1;
        if (ids[mid] < m) lo = mid + 1; else hi = mid;
    }
    off[m] = lo;
}

__global__ void k_mol_mean(const float* __restrict__ atoms,
                           const int* __restrict__ aoff,
                           bf16* __restrict__ mhi, bf16* __restrict__ mlo)
{
    const int m = blockIdx.x, d = threadIdx.x;
    const int s = aoff[m], e = aoff[m + 1];
    float acc = 0.f;
    for (int i = s; i < e; i++) acc += atoms[(size_t)i * D_IN + d];
    float cnt = (float)(e - s);
    if (cnt < 1.f) cnt = 1.f;
    bf16 h, l;
    split1(acc / cnt, h, l);
    mhi[(size_t)m * D_IN + d] = h;
    mlo[(size_t)m * D_IN + d] = l;
}

__global__ void k_init_he0(const float* __restrict__ bo,
                           const float* __restrict__ Wfe,
                           bf16* __restrict__ e0hi, bf16* __restrict__ e0lo)
{
    const int b = blockIdx.x * 2 + (threadIdx.x >> 7);
    const int d = (threadIdx.x & 127) * 2;
    const float o = __ldg(bo + b);
    const float2 wf = __ldg((const float2*)(Wfe + d));
    uint32_t h2, l2;
    split2(tanh_approx(o * wf.x), tanh_approx(o * wf.y), h2, l2);
    const size_t off = (size_t)b * D + d;
    *(uint32_t*)(e0hi + off) = h2;
    *(uint32_t*)(e0lo + off) = l2;
}

// 128 threads, 2 cols per thread, packed loads/stores
__global__ void k_segsum(const bf16* __restrict__ xhi, const bf16* __restrict__ xlo,
                         const int* __restrict__ off,
                         bf16* __restrict__ ohi, bf16* __restrict__ olo)
{
    const int m = blockIdx.x, d2 = threadIdx.x;  // column pair index
    const int s = off[m], e = off[m + 1];
    float a0 = 0.f, a1 = 0.f;
    for (int i = s; i < e; i++) {
        const size_t o = (size_t)i * D + d2 * 2;
        const float2 h = __bfloat1622float2(*(const __nv_bfloat162*)(xhi + o));
        const float2 l = __bfloat1622float2(*(const __nv_bfloat162*)(xlo + o));
        a0 += h.x + l.x;
        a1 += h.y + l.y;
    }
    uint32_t h2, l2;
    split2(a0, a1, h2, l2);
    ((uint32_t*)(ohi + (size_t)m * D))[d2] = h2;
    ((uint32_t*)(olo + (size_t)m * D))[d2] = l2;
}

__global__ void k_f2p(const float* __restrict__ in,
                      bf16* __restrict__ hi, bf16* __restrict__ lo, int n2)
{
    int i = blockIdx.x * blockDim.x + threadIdx.x;
    if (i >= n2) return;
    float2 v = ((const float2*)in)[i];
    uint32_t h2, l2;
    split2(v.x, v.y, h2, l2);
    ((uint32_t*)hi)[i] = h2;
    ((uint32_t*)lo)[i] = l2;
}

struct TransJob { const float* W; bf16* hi; bf16* lo; int K; };
struct TransJobs { TransJob j[5]; };

__global__ void k_transpose_all(TransJobs jobs)
{
    __shared__ float t[32][33];
    const TransJob job = jobs.j[blockIdx.z];
    const int k0 = blockIdx.x * 32;
    if (k0 >= job.K) return;
    const int nb = blockIdx.y * 32;
    const int tx = threadIdx.x, ty = threadIdx.y;
#pragma unroll
    for (int i = 0; i < 4; i++)
        t[ty + 8 * i][tx] = job.W[(size_t)(k0 + ty + 8 * i) * D + nb + tx];
    __syncthreads();
#pragma unroll
    for (int i = 0; i < 4; i++) {
        bf16 h, l;
        split1(t[tx][ty + 8 * i], h, l);
        const size_t o = (size_t)(nb + ty + 8 * i) * job.K + k0 + tx;
        job.hi[o] = h;
        job.lo[o] = l;
    }
}

// ---------------- host orchestration ----------------
static bf16* sym_bf16(const void* sym) {
    void* p = nullptr;
    cudaGetSymbolAddress(&p, sym);
    return (bf16*)p;
}
static float* sym_f32(const void* sym) {
    void* p = nullptr;
    cudaGetSymbolAddress(&p, sym);
    return (float*)p;
}

extern "C" void kernel_launch(void* const* d_in, const int* in_sizes, int n_in,
                              void* d_out, int out_size)
{
    const float* atoms       = (const float*)d_in[0];
    const float* bond_orders = (const float*)d_in[1];
    const int*   bond_src    = (const int*)  d_in[2];
    const int*   bond_dst    = (const int*)  d_in[3];
    const int*   atom_mol    = (const int*)  d_in[4];
    const int*   bond_mol    = (const int*)  d_in[5];
    const float* W_fe        = (const float*)d_in[6];
    const float* W_fv        = (const float*)d_in[7];
    const float* W_fu        = (const float*)d_in[8];
    const float* W_e         = (const float*)d_in[9];
    const float* W_v         = (const float*)d_in[10];
    const float* W_u         = (const float*)d_in[11];

    bf16* he_hi  = sym_bf16(g_he_hi);   bf16* he_lo  = sym_bf16(g_he_lo);
    bf16* he0_hi = sym_bf16(g_he0_hi);  bf16* he0_lo = sym_bf16(g_he0_lo);
    bf16* hv_hi  = sym_bf16(g_hv_hi);   bf16* hv_lo  = sym_bf16(g_hv_lo);
    bf16* hv0_hi = sym_bf16(g_hv0_hi);  bf16* hv0_lo = sym_bf16(g_hv0_lo);
    bf16* hu_hi  = sym_bf16(g_hu_hi);   bf16* hu_lo  = sym_bf16(g_hu_lo);
    bf16* hu0_hi = sym_bf16(g_hu0_hi);  bf16* hu0_lo = sym_bf16(g_hu0_lo);
    bf16* ebar_hi= sym_bf16(g_ebar_hi); bf16* ebar_lo= sym_bf16(g_ebar_lo);
    bf16* vbar_hi= sym_bf16(g_vbar_hi); bf16* vbar_lo= sym_bf16(g_vbar_lo);
    bf16* mm_hi  = sym_bf16(g_mm_hi);   bf16* mm_lo  = sym_bf16(g_mm_lo);
    bf16* at_hi  = sym_bf16(g_at_hi);   bf16* at_lo  = sym_bf16(g_at_lo);
    bf16* we_hi  = sym_bf16(g_we_hi);   bf16* we_lo  = sym_bf16(g_we_lo);
    bf16* wv_hi  = sym_bf16(g_wv_hi);   bf16* wv_lo  = sym_bf16(g_wv_lo);
    bf16* wu_hi  = sym_bf16(g_wu_hi);   bf16* wu_lo  = sym_bf16(g_wu_lo);
    bf16* wfv_hi = sym_bf16(g_wfv_hi);  bf16* wfv_lo = sym_bf16(g_wfv_lo);
    bf16* wfu_hi = sym_bf16(g_wfu_hi);  bf16* wfu_lo = sym_bf16(g_wfu_lo);
    float* ebv_f = sym_f32(g_ebv_f);
    float* E0    = sym_f32(g_E0);
    float* V0t   = sym_f32(g_V0t);
    float* U0    = sym_f32(g_U0);
    float* Ue    = sym_f32(g_Ue);
    float* Uv    = sym_f32(g_Uv);
    float* Vs    = sym_f32(g_Vs);
    float* Vd    = sym_f32(g_Vd);
    int *boff, *aoff;
    { void* p; cudaGetSymbolAddress(&p, g_boff); boff = (int*)p; }
    { void* p; cudaGetSymbolAddress(&p, g_aoff); aoff = (int*)p; }

    const size_t SZ_E = (size_t)N_BONDS * D;
    const size_t SZ_V = (size_t)N_ATOMS * D;
    const size_t SZ_U = (size_t)N_MOLS * D;

    cudaFuncSetAttribute(k_mma, cudaFuncAttributeMaxDynamicSharedMemorySize, SMEM_BYTES);

    static cudaStream_t s1 = nullptr;
    static cudaEvent_t evs[16];
    if (!s1) {
        cudaStreamCreateWithFlags(&s1, cudaStreamNonBlocking);
        for (int i = 0; i < 16; i++) cudaEventCreateWithFlags(&evs[i], cudaEventDisableTiming);
    }

    const Adds noadd = {};
    const Scat noscat = {};

    const int offBlocks = (N_MOLS + 1 + 255) / 256;
    k_offsets2<<<dim3(offBlocks, 2), 256>>>(bond_mol, atom_mol, boff, aoff);
    {
        TransJobs tj;
        tj.j[0] = {W_e,  we_hi,  we_lo,  5 * D};
        tj.j[1] = {W_v,  wv_hi,  wv_lo,  4 * D};
        tj.j[2] = {W_u,  wu_hi,  wu_lo,  4 * D};
        tj.j[3] = {W_fv, wfv_hi, wfv_lo, D_IN};
        tj.j[4] = {W_fu, wfu_hi, wfu_lo, D_IN};
        k_transpose_all<<<dim3(5 * D / 32, 8, 5), dim3(32, 8)>>>(tj);
    }
    k_f2p<<<(int)((N_ATOMS * (size_t)D_IN / 2 + 255) / 256), 256>>>(atoms, at_hi, at_lo,
                                                                    N_ATOMS * D_IN / 2);
    {   // h_v0 = tanh(atoms @ W_fv)
        Srcs s = {};
        s.Ahi[0] = at_hi; s.Alo[0] = at_lo; s.wblk[0] = 0;
        k_mma<<<dim3(2, N_ATOMS / 128), 256, SMEM_BYTES>>>(
            s, D_IN, 2, 4, wfv_hi, wfv_lo, D_IN, wfv_hi, wfv_lo, D_IN,
            noadd, noscat, 1, 0, 0, nullptr, nullptr, hv0_hi, hv0_lo);
    }
    k_init_he0<<<N_BONDS / 2, 256>>>(bond_orders, W_fe, he0_hi, he0_lo);
    k_mol_mean<<<N_MOLS, 128>>>(atoms, aoff, mm_hi, mm_lo);
    cudaMemsetAsync(ebv_f, 0, SZ_V * sizeof(float), 0);

    // fork s1: E0 -> Vs(0) -> V0t
    cudaEventRecord(evs[0], 0);
    cudaStreamWaitEvent(s1, evs[0], 0);
    {   // E0 = he0 @ We[256:512]
        Srcs s = {};
        s.Ahi[0] = he0_hi; s.Alo[0] = he0_lo; s.wblk[0] = 1;
        k_mma<<<dim3(2, N_BONDS / 128), 256, SMEM_BYTES, s1>>>(
            s, D, 3, 8, we_hi, we_lo, 5 * D, we_hi, we_lo, 5 * D,
            noadd, noscat, 0, 0, 0, E0, nullptr, nullptr, nullptr);
    }
    {   // Vs(0) = hv0 @ We[512:768]
        Srcs s = {};
        s.Ahi[0] = hv0_hi; s.Alo[0] = hv0_lo; s.wblk[0] = 2;
        k_mma<<<dim3(2, N_ATOMS / 128), 256, SMEM_BYTES, s1>>>(
            s, D, 3, 8, we_hi, we_lo, 5 * D, we_hi, we_lo, 5 * D,
            noadd, noscat, 0, 0, 0, Vs, nullptr, nullptr, nullptr);
    }
    cudaEventRecord(evs[1], s1);
    {   // V0t = hv0 @ Wv[256:512]
        Srcs s = {};
        s.Ahi[0] = hv0_hi; s.Alo[0] = hv0_lo; s.wblk[0] = 1;
        k_mma<<<dim3(2, N_ATOMS / 128), 256, SMEM_BYTES, s1>>>(
            s, D, 3, 8, wv_hi, wv_lo, 4 * D, wv_hi, wv_lo, 4 * D,
            noadd, noscat, 0, 0, 0, V0t, nullptr, nullptr, nullptr);
    }
    cudaEventRecord(evs[2], s1);

    // main: hu0, U0+Ue, Uv, Vd(0)
    {   // h_u0 = tanh(mol_mean @ W_fu)
        Srcs s = {};
        s.Ahi[0] = mm_hi; s.Alo[0] = mm_lo; s.wblk[0] = 0;
        k_mma<<<dim3(2, N_MOLS / 128), 256, SMEM_BYTES>>>(
            s, D_IN, 2, 4, wfu_hi, wfu_lo, D_IN, wfu_hi, wfu_lo, D_IN,
            noadd, noscat, 1, 0, 0, nullptr, nullptr, hu0_hi, hu0_lo);
    }
    {   // merged: U0 | Ue(0)
        Srcs s = {};
        s.Ahi[0] = hu0_hi; s.Alo[0] = hu0_lo; s.wblk[0] = 1;
        k_mma<<<dim3(2, 2 * N_MOLS / 128), 256, SMEM_BYTES>>>(
            s, D, 3, 8, wu_hi, wu_lo, 4 * D, we_hi, we_lo, 5 * D,
            noadd, noscat, 0, N_MOLS / 128, 4, U0, Ue, nullptr, nullptr);
    }
    {   // Uv(0)
        Srcs s = {};
        s.Ahi[0] = hu0_hi; s.Alo[0] = hu0_lo; s.wblk[0] = 3;
        k_mma<<<dim3(2, N_MOLS / 128), 256, SMEM_BYTES>>>(
            s, D, 3, 8, wv_hi, wv_lo, 4 * D, wv_hi, wv_lo, 4 * D,
            noadd, noscat, 0, 0, 0, Uv, nullptr, nullptr, nullptr);
    }
    {   // Vd(0)
        Srcs s = {};
        s.Ahi[0] = hv0_hi; s.Alo[0] = hv0_lo; s.wblk[0] = 3;
        k_mma<<<dim3(2, N_ATOMS / 128), 256, SMEM_BYTES>>>(
            s, D, 3, 8, we_hi, we_lo, 5 * D, we_hi, we_lo, 5 * D,
            noadd, noscat, 0, 0, 0, Vd, nullptr, nullptr, nullptr);
    }

    const bf16 *cur_he_hi = he0_hi, *cur_he_lo = he0_lo;
    const bf16 *cur_hv_hi = hv0_hi, *cur_hv_lo = hv0_lo;
    const bf16 *cur_hu_hi = hu0_hi, *cur_hu_lo = hu0_lo;

    cudaStreamWaitEvent(0, evs[1], 0);

    int evi = 3;
    int hebuf = 0, hvbuf = 0, hubuf = 0;
    for (int it = 0; it < 3; it++) {
        // edge update (fused gathers + scatter)
        {
            Srcs s = {};
            s.Ahi[0] = cur_he_hi;  s.Alo[0] = cur_he_lo;  s.wblk[0] = 0;
            Adds a = {};
            a.direct = E0;
            a.gat[0] = Ue; a.gidx[0] = bond_mol;
            a.gat[1] = Vs; a.gidx[1] = bond_src;
            a.gat[2] = Vd; a.gidx[2] = bond_dst;
            if (it == 2) {
                k_mma<<<dim3(2, N_BONDS / 128), 256, SMEM_BYTES>>>(
                    s, D, 3, 8, we_hi, we_lo, 5 * D, we_hi, we_lo, 5 * D,
                    a, noscat, 2, 0, 0, (float*)d_out, nullptr, nullptr, nullptr);
                break;
            }
            Scat sc = {ebv_f, bond_src, bond_dst};
            bf16* nh = he_hi + (size_t)hebuf * SZ_E;
            bf16* nl = he_lo + (size_t)hebuf * SZ_E;
            k_mma<<<dim3(2, N_BONDS / 128), 256, SMEM_BYTES>>>(
                s, D, 3, 8, we_hi, we_lo, 5 * D, we_hi, we_lo, 5 * D,
                a, sc, 1, 0, 0, nullptr, nullptr, nh, nl);
            cur_he_hi = nh; cur_he_lo = nl;
            hebuf ^= 1;
        }

        // fork: he-segsum on s1
        cudaEventRecord(evs[evi], 0);
        cudaStreamWaitEvent(s1, evs[evi], 0);
        k_segsum<<<N_MOLS, 128, 0, s1>>>(cur_he_hi, cur_he_lo, boff, ebar_hi, ebar_lo);
        cudaEventRecord(evs[evi + 1], s1);

        // node update (it==0 needs V0t)
        if (it == 0) cudaStreamWaitEvent(0, evs[2], 0);
        {
            Srcs s = {};
            s.Ahi[0] = cur_hv_hi;  s.Alo[0] = cur_hv_lo;  s.wblk[0] = 0;
            s.Ahi[1] = ebv_f;  s.wblk[1] = 2;  s.isf32[1] = 1;
            Adds a = {};
            a.direct = V0t;
            a.gat[0] = Uv; a.gidx[0] = atom_mol;
            bf16* nh = hv_hi + (size_t)hvbuf * SZ_V;
            bf16* nl = hv_lo + (size_t)hvbuf * SZ_V;
            k_mma<<<dim3(2, N_ATOMS / 128), 256, SMEM_BYTES>>>(
                s, D, 3, 16, wv_hi, wv_lo, 4 * D, wv_hi, wv_lo, 4 * D,
                a, noscat, 1, 0, 0, nullptr, nullptr, nh, nl);
            cur_hv_hi = nh; cur_hv_lo = nl;
            hvbuf ^= 1;
        }

        // fork: ebv clear + Vs(it+1) on s1 (ordered after node GEMM)
        cudaEventRecord(evs[evi + 2], 0);
        cudaStreamWaitEvent(s1, evs[evi + 2], 0);
        if (it == 0)
            cudaMemsetAsync(ebv_f, 0, SZ_V * sizeof(float), s1);
        {
            Srcs s = {};
            s.Ahi[0] = cur_hv_hi;  s.Alo[0] = cur_hv_lo;  s.wblk[0] = 2;
            k_mma<<<dim3(2, N_ATOMS / 128), 256, SMEM_BYTES, s1>>>(
                s, D, 3, 8, we_hi, we_lo, 5 * D, we_hi, we_lo, 5 * D,
                noadd, noscat, 0, 0, 0, Vs, nullptr, nullptr, nullptr);
        }
        cudaEventRecord(evs[evi + 3], s1);

        // main: hv-segsum, global, Ue(+Uv), Vd(it+1)
        k_segsum<<<N_MOLS, 128>>>(cur_hv_hi, cur_hv_lo, aoff, vbar_hi, vbar_lo);
        cudaStreamWaitEvent(0, evs[evi + 1], 0);
        {
            Srcs s = {};
            s.Ahi[0] = cur_hu_hi;  s.Alo[0] = cur_hu_lo;  s.wblk[0] = 0;
            s.Ahi[1] = ebar_hi;  s.Alo[1] = ebar_lo;  s.wblk[1] = 2;
            s.Ahi[2] = vbar_hi;  s.Alo[2] = vbar_lo;  s.wblk[2] = 3;
            Adds a = {};
            a.direct = U0;
            bf16* nh = hu_hi + (size_t)hubuf * SZ_U;
            bf16* nl = hu_lo + (size_t)hubuf * SZ_U;
            k_mma<<<dim3(2, N_MOLS / 128), 256, SMEM_BYTES>>>(
                s, D, 3, 24, wu_hi, wu_lo, 4 * D, wu_hi, wu_lo, 4 * D,
                a, noscat, 1, 0, 0, nullptr, nullptr, nh, nl);
            cur_hu_hi = nh; cur_hu_lo = nl;
            hubuf ^= 1;
        }
        {
            Srcs s = {};
            s.Ahi[0] = cur_hu_hi; s.Alo[0] = cur_hu_lo; s.wblk[0] = 4;
            if (it + 1 < 2) {
                k_mma<<<dim3(2, 2 * N_MOLS / 128), 256, SMEM_BYTES>>>(
                    s, D, 3, 8, we_hi, we_lo, 5 * D, wv_hi, wv_lo, 4 * D,
                    noadd, noscat, 0, N_MOLS / 128, 3, Ue, Uv, nullptr, nullptr);
            } else {
                k_mma<<<dim3(2, N_MOLS / 128), 256, SMEM_BYTES>>>(
                    s, D, 3, 8, we_hi, we_lo, 5 * D, we_hi, we_lo, 5 * D,
                    noadd, noscat, 0, 0, 0, Ue, nullptr, nullptr, nullptr);
            }
        }
        {   // Vd(it+1) on main
            Srcs s = {};
            s.Ahi[0] = cur_hv_hi;  s.Alo[0] = cur_hv_lo;  s.wblk[0] = 3;
            k_mma<<<dim3(2, N_ATOMS / 128), 256, SMEM_BYTES>>>(
                s, D, 3, 8, we_hi, we_lo, 5 * D, we_hi, we_lo, 5 * D,
                noadd, noscat, 0, 0, 0, Vd, nullptr, nullptr, nullptr);
        }
        // join s1 before next edge
        cudaStreamWaitEvent(0, evs[evi + 3], 0);
        evi += 4;
    }
}

// round 16
// speedup vs baseline: 1.0178x; 1.0178x over previous
#include <cuda_runtime.h>
#include <cuda_bf16.h>
#include <math.h>
#include <stdint.h>

typedef __nv_bfloat16 bf16;

#define N_ATOMS 65536
#define N_BONDS 98304
#define N_MOLS  4096
#define D_IN    128
#define D       256

// ---------------- scratch (device globals; no allocation allowed) ----------------
__device__ bf16 g_he_hi [2][(size_t)N_BONDS * D];
__device__ bf16 g_he_lo [2][(size_t)N_BONDS * D];
__device__ bf16 g_he0_hi[(size_t)N_BONDS * D];
__device__ bf16 g_he0_lo[(size_t)N_BONDS * D];
__device__ bf16 g_hv_hi [2][(size_t)N_ATOMS * D];
__device__ bf16 g_hv_lo [2][(size_t)N_ATOMS * D];
__device__ bf16 g_hv0_hi[(size_t)N_ATOMS * D];
__device__ bf16 g_hv0_lo[(size_t)N_ATOMS * D];
__device__ float g_ebv_f [(size_t)N_ATOMS * D];
__device__ bf16 g_hu_hi [2][(size_t)N_MOLS * D];
__device__ bf16 g_hu_lo [2][(size_t)N_MOLS * D];
__device__ bf16 g_hu0_hi[(size_t)N_MOLS * D];
__device__ bf16 g_hu0_lo[(size_t)N_MOLS * D];
__device__ bf16 g_ebar_hi[(size_t)N_MOLS * D];
__device__ bf16 g_ebar_lo[(size_t)N_MOLS * D];
__device__ bf16 g_vbar_hi[(size_t)N_MOLS * D];
__device__ bf16 g_vbar_lo[(size_t)N_MOLS * D];
__device__ bf16 g_mm_hi [(size_t)N_MOLS * D_IN];
__device__ bf16 g_mm_lo [(size_t)N_MOLS * D_IN];
__device__ bf16 g_at_hi [(size_t)N_ATOMS * D_IN];
__device__ bf16 g_at_lo [(size_t)N_ATOMS * D_IN];
__device__ bf16 g_we_hi [(size_t)D * 5 * D];
__device__ bf16 g_we_lo [(size_t)D * 5 * D];
__device__ bf16 g_wv_hi [(size_t)D * 4 * D];
__device__ bf16 g_wv_lo [(size_t)D * 4 * D];
__device__ bf16 g_wu_hi [(size_t)D * 4 * D];
__device__ bf16 g_wu_lo [(size_t)D * 4 * D];
__device__ bf16 g_wfv_hi[(size_t)D * D_IN];
__device__ bf16 g_wfv_lo[(size_t)D * D_IN];
__device__ bf16 g_wfu_hi[(size_t)D * D_IN];
__device__ bf16 g_wfu_lo[(size_t)D * D_IN];
// precomputed fp32 epilogue-add terms
__device__ float g_E0 [(size_t)N_BONDS * D];
__device__ float g_V0t[(size_t)N_ATOMS * D];
__device__ float g_U0 [(size_t)N_MOLS * D];
__device__ float g_Ue [(size_t)N_MOLS * D];
__device__ float g_Uv [(size_t)N_MOLS * D];
__device__ float g_Vs [(size_t)N_ATOMS * D];
__device__ float g_Vd [(size_t)N_ATOMS * D];
__device__ int  g_boff[N_MOLS + 1];
__device__ int  g_aoff[N_MOLS + 1];

// ---------------- helpers ----------------
__device__ __forceinline__ uint32_t smem_u32(const void* p) {
    uint32_t a;
    asm("{ .reg .u64 t; cvta.to.shared.u64 t, %1; cvt.u32.u64 %0, t; }" : "=r"(a) : "l"(p));
    return a;
}
__device__ __forceinline__ void cp16(uint32_t dst, const void* src) {
    asm volatile("cp.async.cg.shared.global [%0], [%1], 16;" :: "r"(dst), "l"(src) : "memory");
}
#define CP_COMMIT()  asm volatile("cp.async.commit_group;" ::: "memory")
#define CP_WAIT0()   asm volatile("cp.async.wait_group 0;" ::: "memory")

__device__ __forceinline__ void ldsm4(uint32_t* r, uint32_t addr) {
    asm volatile("ldmatrix.sync.aligned.m8n8.x4.shared.b16 {%0,%1,%2,%3}, [%4];"
        : "=r"(r[0]), "=r"(r[1]), "=r"(r[2]), "=r"(r[3]) : "r"(addr));
}
__device__ __forceinline__ void mma_bf16(float* c, const uint32_t* a, const uint32_t* b) {
    asm volatile(
        "mma.sync.aligned.m16n8k16.row.col.f32.bf16.bf16.f32 "
        "{%0,%1,%2,%3}, {%4,%5,%6,%7}, {%8,%9}, {%0,%1,%2,%3};"
        : "+f"(c[0]), "+f"(c[1]), "+f"(c[2]), "+f"(c[3])
        : "r"(a[0]), "r"(a[1]), "r"(a[2]), "r"(a[3]), "r"(b[0]), "r"(b[1]));
}
__device__ __forceinline__ void red2(float* p, float a, float b) {
    asm volatile("red.global.add.v2.f32 [%0], {%1,%2};"
        :: "l"(p), "f"(a), "f"(b) : "memory");
}
__device__ __forceinline__ void split1(float v, bf16& h, bf16& l) {
    h = __float2bfloat16(v);
    l = __float2bfloat16(v - __bfloat162float(h));
}
// packed split: 2 cvt + shl/and + 2 sub per PAIR of values
__device__ __forceinline__ void split2(float v0, float v1, uint32_t& h2, uint32_t& l2) {
    asm("cvt.rn.bf16x2.f32 %0, %1, %2;" : "=r"(h2) : "f"(v1), "f"(v0));
    const float f0 = __uint_as_float(h2 << 16);
    const float f1 = __uint_as_float(h2 & 0xffff0000u);
    const float l0 = v0 - f0;
    const float l1 = v1 - f1;
    asm("cvt.rn.bf16x2.f32 %0, %1, %2;" : "=r"(l2) : "f"(l1), "f"(l0));
}
__device__ __forceinline__ float tanh_approx(float x) {
    float y;
    asm("tanh.approx.f32 %0, %1;" : "=f"(y) : "f"(x));
    return y;
}
__device__ __forceinline__ float tanh_precise(float x) {
    const float e = __expf(2.0f * x);
    return 1.0f - __fdividef(2.0f, e + 1.0f);
}

// ---------------- fused multi-source bf16x3 GEMM (+adds, +scatter, +tanh) ---------
struct Srcs {
    const void* Ahi[4];
    const void* Alo[4];
    const int*  idx[4];
    int         wblk[4];
    int         isf32[4];
};
struct Adds {
    const float* direct;
    const float* gat[3];
    const int*   gidx[3];
};
struct Scat {
    float*     buf;
    const int* i0;
    const int* i1;
};

#define TILE_B   10240
#define SM_A     0
#define SM_B     40960
#define SMEM_BYTES 81920

__global__ void __launch_bounds__(256, 2)
k_mma(Srcs srcs, int ksrc, int cshift, int n_chunks,
      const bf16* __restrict__ Whi, const bf16* __restrict__ Wlo, int kstride,
      const bf16* __restrict__ Whi2, const bf16* __restrict__ Wlo2, int kstride2,
      Adds adds, Scat scat, int do_tanh,
      int ysplit, int wblk_alt,
      float* __restrict__ out_f32, float* __restrict__ out_alt,
      bf16* __restrict__ out_hi, bf16* __restrict__ out_lo)
{
    extern __shared__ char smc[];
    const uint32_t smu = smem_u32(smc);

    const int tid  = threadIdx.x;
    const int lane = tid & 31;
    const int w    = tid >> 5;
    const int wm   = w & 3;
    const int wn   = w >> 2;
    const int lr   = lane >> 2;
    const int lc   = lane & 3;

    const int n0 = blockIdx.x * 128;
    const int yb = blockIdx.y;
    const bool alt = (ysplit > 0) && (yb >= ysplit);
    const int m0 = (alt ? yb - ysplit : yb) * 128;

    const int cmask = (ksrc >> 5) - 1;

    const int r8 = lane & 7, j8 = lane >> 3;
    const uint32_t offA = (uint32_t)((r8 + (j8 & 1) * 8) * 80 + ((j8 >> 1) & 1) * 16)
                        + (uint32_t)(wm * 32) * 80u;
    const uint32_t offB = (uint32_t)(r8 * 80 + ((j8 >> 1) & 1) * 640 + (j8 & 1) * 16)
                        + (uint32_t)(wn * 64) * 80u;

    const int arow = tid >> 1;
    const int apl  = tid & 1;
    int cur_s = -1, is32 = 0, wcur = 0;
    const bf16*  aptr = nullptr;
    const float* a32  = nullptr;
    const bf16* wbase = alt ? (apl ? Wlo2 : Whi2) : (apl ? Wlo : Whi);
    const int   kstr  = alt ? kstride2 : kstride;

    auto load_chunk = [&](int c) {
        const int buf = c & 1;
        const int s = c >> cshift;
        if (s != cur_s) {
            cur_s = s;
            is32 = srcs.isf32[s];
            int gr = m0 + arow;
            const int* ix = srcs.idx[s];
            if (ix) gr = __ldg(ix + gr);
            if (is32) a32 = (const float*)srcs.Ahi[s] + (size_t)gr * ksrc;
            else aptr = (const bf16*)(apl ? srcs.Alo[s] : srcs.Ahi[s]) + (size_t)gr * ksrc;
            wcur = (s == 0 && alt) ? wblk_alt : srcs.wblk[s];
        }
        const uint32_t ad = smu + (uint32_t)(SM_A + apl * 2 * TILE_B + buf * TILE_B + arow * 80);
        if (is32) {
            const float* fs = a32 + ((c & cmask) << 5);
#pragma unroll
            for (int i = 0; i < 4; i++) {
                float4 x = __ldg((const float4*)(fs + i * 8));
                float4 y = __ldg((const float4*)(fs + i * 8 + 4));
                uint32_t h, l, r0, r1, r2, r3;
                split2(x.x, x.y, h, l); r0 = apl ? l : h;
                split2(x.z, x.w, h, l); r1 = apl ? l : h;
                split2(y.x, y.y, h, l); r2 = apl ? l : h;
                split2(y.z, y.w, h, l); r3 = apl ? l : h;
                asm volatile("st.shared.v4.b32 [%0], {%1,%2,%3,%4};"
                    :: "r"(ad + (uint32_t)(i * 16)), "r"(r0), "r"(r1), "r"(r2), "r"(r3)
                    : "memory");
            }
        } else {
            const bf16* as = aptr + ((c & cmask) << 5);
            cp16(ad,      as);
            cp16(ad + 16, as + 8);
            cp16(ad + 32, as + 16);
            cp16(ad + 48, as + 24);
        }
        const bf16* bs = wbase + (size_t)(n0 + arow) * kstr
                       + (wcur << 8) + ((c & cmask) << 5);
        const uint32_t bd = smu + (uint32_t)(SM_B + apl * 2 * TILE_B + buf * TILE_B + arow * 80);
        cp16(bd,      bs);
        cp16(bd + 16, bs + 8);
        cp16(bd + 32, bs + 16);
        cp16(bd + 48, bs + 24);
    };

    float acc[2][8][4];
#pragma unroll
    for (int mi = 0; mi < 2; mi++)
#pragma unroll
        for (int nj = 0; nj < 8; nj++)
#pragma unroll
            for (int q = 0; q < 4; q++) acc[mi][nj][q] = 0.f;

    load_chunk(0);
    CP_COMMIT();

    for (int c = 0; c < n_chunks; c++) {
        CP_WAIT0();
        __syncthreads();
        if (c + 1 < n_chunks) load_chunk(c + 1);
        CP_COMMIT();

        const int buf = c & 1;
        const uint32_t aH = smu + SM_A + (uint32_t)(buf * TILE_B);
        const uint32_t aL = aH + 2u * TILE_B;
        const uint32_t bH = smu + SM_B + (uint32_t)(buf * TILE_B);
        const uint32_t bL = bH + 2u * TILE_B;

#pragma unroll
        for (int ks = 0; ks < 2; ks++) {
            const uint32_t kb = (uint32_t)(ks * 32);
            uint32_t ah[2][4], al[2][4];
            ldsm4(ah[0], aH + offA + kb);
            ldsm4(ah[1], aH + offA + 1280u + kb);
            ldsm4(al[0], aL + offA + kb);
            ldsm4(al[1], aL + offA + 1280u + kb);
#pragma unroll
            for (int g = 0; g < 2; g++) {
                const uint32_t go = (uint32_t)(g * 2560);
                uint32_t bh[4][2], bl[4][2];
                ldsm4(&bh[0][0], bH + offB + go + kb);
                ldsm4(&bh[2][0], bH + offB + go + 1280u + kb);
                ldsm4(&bl[0][0], bL + offB + go + kb);
                ldsm4(&bl[2][0], bL + offB + go + 1280u + kb);
#pragma unroll
                for (int mi = 0; mi < 2; mi++)
#pragma unroll
                    for (int q = 0; q < 4; q++) {
                        float* acq = acc[mi][g * 4 + q];
                        mma_bf16(acq, ah[mi], bh[q]);
                        mma_bf16(acq, ah[mi], bl[q]);
                        mma_bf16(acq, al[mi], bh[q]);
                    }
            }
        }
        __syncthreads();
    }

    float* outf = alt ? out_alt : out_f32;

    // epilogue
#pragma unroll
    for (int mi = 0; mi < 2; mi++) {
        const int r0 = m0 + wm * 32 + mi * 16 + lr;
        const int r1 = r0 + 8;
        const float* dp0 = adds.direct ? adds.direct + (size_t)r0 * D : nullptr;
        const float* dp1 = adds.direct ? adds.direct + (size_t)r1 * D : nullptr;
        const float* gp[3][2];
#pragma unroll
        for (int t = 0; t < 3; t++) {
            if (adds.gat[t]) {
                gp[t][0] = adds.gat[t] + (size_t)__ldg(adds.gidx[t] + r0) * D;
                gp[t][1] = adds.gat[t] + (size_t)__ldg(adds.gidx[t] + r1) * D;
            } else {
                gp[t][0] = nullptr; gp[t][1] = nullptr;
            }
        }
        float *s00 = nullptr, *s01 = nullptr, *s10 = nullptr, *s11 = nullptr;
        if (scat.buf) {
            s00 = scat.buf + (size_t)__ldg(scat.i0 + r0) * D;
            s01 = scat.buf + (size_t)__ldg(scat.i0 + r1) * D;
            s10 = scat.buf + (size_t)__ldg(scat.i1 + r0) * D;
            s11 = scat.buf + (size_t)__ldg(scat.i1 + r1) * D;
        }
#pragma unroll
        for (int nj = 0; nj < 8; nj++) {
            const int col = n0 + wn * 64 + nj * 8 + lc * 2;
            float v0 = acc[mi][nj][0];
            float v1 = acc[mi][nj][1];
            float v2 = acc[mi][nj][2];
            float v3 = acc[mi][nj][3];
            if (dp0) {
                float2 t0 = *(const float2*)(dp0 + col);
                float2 t1 = *(const float2*)(dp1 + col);
                v0 += t0.x; v1 += t0.y; v2 += t1.x; v3 += t1.y;
            }
#pragma unroll
            for (int t = 0; t < 3; t++) {
                if (gp[t][0]) {
                    float2 t0 = *(const float2*)(gp[t][0] + col);
                    float2 t1 = *(const float2*)(gp[t][1] + col);
                    v0 += t0.x; v1 += t0.y; v2 += t1.x; v3 += t1.y;
                }
            }
            if (do_tanh == 1) {
                v0 = tanh_approx(v0); v1 = tanh_approx(v1);
                v2 = tanh_approx(v2); v3 = tanh_approx(v3);
            } else if (do_tanh == 2) {
                v0 = tanh_precise(v0); v1 = tanh_precise(v1);
                v2 = tanh_precise(v2); v3 = tanh_precise(v3);
            }
            if (s00) {
                red2(s00 + col, v0, v1);
                red2(s10 + col, v0, v1);
                red2(s01 + col, v2, v3);
                red2(s11 + col, v2, v3);
            }
            if (outf) {
                *(float2*)(outf + (size_t)r0 * D + col) = make_float2(v0, v1);
                *(float2*)(outf + (size_t)r1 * D + col) = make_float2(v2, v3);
            }
            if (out_hi) {
                uint32_t h01, l01, h23, l23;
                split2(v0, v1, h01, l01);
                split2(v2, v3, h23, l23);
                const size_t o0 = (size_t)r0 * D + col;
                const size_t o1 = (size_t)r1 * D + col;
                *(uint32_t*)(out_hi + o0) = h01;  *(uint32_t*)(out_lo + o0) = l01;
                *(uint32_t*)(out_hi + o1) = h23;  *(uint32_t*)(out_lo + o1) = l23;
            }
        }
    }
}

// ---------------- small kernels ----------------
__global__ void k_offsets2(const int* __restrict__ bids, const int* __restrict__ aids,
                           int* __restrict__ boff, int* __restrict__ aoff)
{
    int m = blockIdx.x * blockDim.x + threadIdx.x;
    if (m > N_MOLS) return;
    const int* ids = blockIdx.y ? aids : bids;
    const int n    = blockIdx.y ? N_ATOMS : N_BONDS;
    int* off       = blockIdx.y ? aoff : boff;
    int lo = 0, hi = n;
    while (lo < hi) {
        int mid = (lo + hi) >> 1;
        if (ids[mid] < m) lo = mid + 1; else hi = mid;
    }
    off[m] = lo;
}

__global__ void k_mol_mean(const float* __restrict__ atoms,
                           const int* __restrict__ aoff,
                           bf16* __restrict__ mhi, bf16* __restrict__ mlo)
{
    const int m = blockIdx.x, d = threadIdx.x;
    const int s = aoff[m], e = aoff[m + 1];
    float acc = 0.f;
    for (int i = s; i < e; i++) acc += atoms[(size_t)i * D_IN + d];
    float cnt = (float)(e - s);
    if (cnt < 1.f) cnt = 1.f;
    bf16 h, l;
    split1(acc / cnt, h, l);
    mhi[(size_t)m * D_IN + d] = h;
    mlo[(size_t)m * D_IN + d] = l;
}

__global__ void k_init_he0(const float* __restrict__ bo,
                           const float* __restrict__ Wfe,
                           bf16* __restrict__ e0hi, bf16* __restrict__ e0lo)
{
    const int b = blockIdx.x * 2 + (threadIdx.x >> 7);
    const int d = (threadIdx.x & 127) * 2;
    const float o = __ldg(bo + b);
    const float2 wf = __ldg((const float2*)(Wfe + d));
    uint32_t h2, l2;
    split2(tanh_approx(o * wf.x), tanh_approx(o * wf.y), h2, l2);
    const size_t off = (size_t)b * D + d;
    *(uint32_t*)(e0hi + off) = h2;
    *(uint32_t*)(e0lo + off) = l2;
}

// 128 threads, 2 cols per thread, packed loads/stores
__global__ void k_segsum(const bf16* __restrict__ xhi, const bf16* __restrict__ xlo,
                         const int* __restrict__ off,
                         bf16* __restrict__ ohi, bf16* __restrict__ olo)
{
    const int m = blockIdx.x, d2 = threadIdx.x;
    const int s = off[m], e = off[m + 1];
    float a0 = 0.f, a1 = 0.f;
    for (int i = s; i < e; i++) {
        const size_t o = (size_t)i * D + d2 * 2;
        const float2 h = __bfloat1622float2(*(const __nv_bfloat162*)(xhi + o));
        const float2 l = __bfloat1622float2(*(const __nv_bfloat162*)(xlo + o));
        a0 += h.x + l.x;
        a1 += h.y + l.y;
    }
    uint32_t h2, l2;
    split2(a0, a1, h2, l2);
    ((uint32_t*)(ohi + (size_t)m * D))[d2] = h2;
    ((uint32_t*)(olo + (size_t)m * D))[d2] = l2;
}

__global__ void k_f2p(const float* __restrict__ in,
                      bf16* __restrict__ hi, bf16* __restrict__ lo, int n2)
{
    int i = blockIdx.x * blockDim.x + threadIdx.x;
    if (i >= n2) return;
    float2 v = ((const float2*)in)[i];
    uint32_t h2, l2;
    split2(v.x, v.y, h2, l2);
    ((uint32_t*)hi)[i] = h2;
    ((uint32_t*)lo)[i] = l2;
}

struct TransJob { const float* W; bf16* hi; bf16* lo; int K; };
struct TransJobs { TransJob j[5]; };

__global__ void k_transpose_all(TransJobs jobs)
{
    __shared__ float t[32][33];
    const TransJob job = jobs.j[blockIdx.z];
    const int k0 = blockIdx.x * 32;
    if (k0 >= job.K) return;
    const int nb = blockIdx.y * 32;
    const int tx = threadIdx.x, ty = threadIdx.y;
#pragma unroll
    for (int i = 0; i < 4; i++)
        t[ty + 8 * i][tx] = job.W[(size_t)(k0 + ty + 8 * i) * D + nb + tx];
    __syncthreads();
#pragma unroll
    for (int i = 0; i < 4; i++) {
        bf16 h, l;
        split1(t[tx][ty + 8 * i], h, l);
        const size_t o = (size_t)(nb + ty + 8 * i) * job.K + k0 + tx;
        job.hi[o] = h;
        job.lo[o] = l;
    }
}

// ---------------- host orchestration ----------------
static bf16* sym_bf16(const void* sym) {
    void* p = nullptr;
    cudaGetSymbolAddress(&p, sym);
    return (bf16*)p;
}
static float* sym_f32(const void* sym) {
    void* p = nullptr;
    cudaGetSymbolAddress(&p, sym);
    return (float*)p;
}

extern "C" void kernel_launch(void* const* d_in, const int* in_sizes, int n_in,
                              void* d_out, int out_size)
{
    const float* atoms       = (const float*)d_in[0];
    const float* bond_orders = (const float*)d_in[1];
    const int*   bond_src    = (const int*)  d_in[2];
    const int*   bond_dst    = (const int*)  d_in[3];
    const int*   atom_mol    = (const int*)  d_in[4];
    const int*   bond_mol    = (const int*)  d_in[5];
    const float* W_fe        = (const float*)d_in[6];
    const float* W_fv        = (const float*)d_in[7];
    const float* W_fu        = (const float*)d_in[8];
    const float* W_e         = (const float*)d_in[9];
    const float* W_v         = (const float*)d_in[10];
    const float* W_u         = (const float*)d_in[11];

    bf16* he_hi  = sym_bf16(g_he_hi);   bf16* he_lo  = sym_bf16(g_he_lo);
    bf16* he0_hi = sym_bf16(g_he0_hi);  bf16* he0_lo = sym_bf16(g_he0_lo);
    bf16* hv_hi  = sym_bf16(g_hv_hi);   bf16* hv_lo  = sym_bf16(g_hv_lo);
    bf16* hv0_hi = sym_bf16(g_hv0_hi);  bf16* hv0_lo = sym_bf16(g_hv0_lo);
    bf16* hu_hi  = sym_bf16(g_hu_hi);   bf16* hu_lo  = sym_bf16(g_hu_lo);
    bf16* hu0_hi = sym_bf16(g_hu0_hi);  bf16* hu0_lo = sym_bf16(g_hu0_lo);
    bf16* ebar_hi= sym_bf16(g_ebar_hi); bf16* ebar_lo= sym_bf16(g_ebar_lo);
    bf16* vbar_hi= sym_bf16(g_vbar_hi); bf16* vbar_lo= sym_bf16(g_vbar_lo);
    bf16* mm_hi  = sym_bf16(g_mm_hi);   bf16* mm_lo  = sym_bf16(g_mm_lo);
    bf16* at_hi  = sym_bf16(g_at_hi);   bf16* at_lo  = sym_bf16(g_at_lo);
    bf16* we_hi  = sym_bf16(g_we_hi);   bf16* we_lo  = sym_bf16(g_we_lo);
    bf16* wv_hi  = sym_bf16(g_wv_hi);   bf16* wv_lo  = sym_bf16(g_wv_lo);
    bf16* wu_hi  = sym_bf16(g_wu_hi);   bf16* wu_lo  = sym_bf16(g_wu_lo);
    bf16* wfv_hi = sym_bf16(g_wfv_hi);  bf16* wfv_lo = sym_bf16(g_wfv_lo);
    bf16* wfu_hi = sym_bf16(g_wfu_hi);  bf16* wfu_lo = sym_bf16(g_wfu_lo);
    float* ebv_f = sym_f32(g_ebv_f);
    float* E0    = sym_f32(g_E0);
    float* V0t   = sym_f32(g_V0t);
    float* U0    = sym_f32(g_U0);
    float* Ue    = sym_f32(g_Ue);
    float* Uv    = sym_f32(g_Uv);
    float* Vs    = sym_f32(g_Vs);
    float* Vd    = sym_f32(g_Vd);
    int *boff, *aoff;
    { void* p; cudaGetSymbolAddress(&p, g_boff); boff = (int*)p; }
    { void* p; cudaGetSymbolAddress(&p, g_aoff); aoff = (int*)p; }

    const size_t SZ_E = (size_t)N_BONDS * D;
    const size_t SZ_V = (size_t)N_ATOMS * D;
    const size_t SZ_U = (size_t)N_MOLS * D;

    cudaFuncSetAttribute(k_mma, cudaFuncAttributeMaxDynamicSharedMemorySize, SMEM_BYTES);

    static cudaStream_t s1 = nullptr;
    static cudaEvent_t evs[16];
    if (!s1) {
        cudaStreamCreateWithFlags(&s1, cudaStreamNonBlocking);
        for (int i = 0; i < 16; i++) cudaEventCreateWithFlags(&evs[i], cudaEventDisableTiming);
    }

    const Adds noadd = {};
    const Scat noscat = {};

    const int offBlocks = (N_MOLS + 1 + 255) / 256;
    k_offsets2<<<dim3(offBlocks, 2), 256>>>(bond_mol, atom_mol, boff, aoff);
    {
        TransJobs tj;
        tj.j[0] = {W_e,  we_hi,  we_lo,  5 * D};
        tj.j[1] = {W_v,  wv_hi,  wv_lo,  4 * D};
        tj.j[2] = {W_u,  wu_hi,  wu_lo,  4 * D};
        tj.j[3] = {W_fv, wfv_hi, wfv_lo, D_IN};
        tj.j[4] = {W_fu, wfu_hi, wfu_lo, D_IN};
        k_transpose_all<<<dim3(5 * D / 32, 8, 5), dim3(32, 8)>>>(tj);
    }
    k_f2p<<<(int)((N_ATOMS * (size_t)D_IN / 2 + 255) / 256), 256>>>(atoms, at_hi, at_lo,
                                                                    N_ATOMS * D_IN / 2);
    {   // h_v0 = tanh(atoms @ W_fv)
        Srcs s = {};
        s.Ahi[0] = at_hi; s.Alo[0] = at_lo; s.wblk[0] = 0;
        k_mma<<<dim3(2, N_ATOMS / 128), 256, SMEM_BYTES>>>(
            s, D_IN, 2, 4, wfv_hi, wfv_lo, D_IN, wfv_hi, wfv_lo, D_IN,
            noadd, noscat, 1, 0, 0, nullptr, nullptr, hv0_hi, hv0_lo);
    }
    k_init_he0<<<N_BONDS / 2, 256>>>(bond_orders, W_fe, he0_hi, he0_lo);
    k_mol_mean<<<N_MOLS, 128>>>(atoms, aoff, mm_hi, mm_lo);
    cudaMemsetAsync(ebv_f, 0, SZ_V * sizeof(float), 0);

    // fork s1: E0 -> Vs(0) -> V0t
    cudaEventRecord(evs[0], 0);
    cudaStreamWaitEvent(s1, evs[0], 0);
    {   // E0 = he0 @ We[256:512]
        Srcs s = {};
        s.Ahi[0] = he0_hi; s.Alo[0] = he0_lo; s.wblk[0] = 1;
        k_mma<<<dim3(2, N_BONDS / 128), 256, SMEM_BYTES, s1>>>(
            s, D, 3, 8, we_hi, we_lo, 5 * D, we_hi, we_lo, 5 * D,
            noadd, noscat, 0, 0, 0, E0, nullptr, nullptr, nullptr);
    }
    {   // Vs(0) = hv0 @ We[512:768]
        Srcs s = {};
        s.Ahi[0] = hv0_hi; s.Alo[0] = hv0_lo; s.wblk[0] = 2;
        k_mma<<<dim3(2, N_ATOMS / 128), 256, SMEM_BYTES, s1>>>(
            s, D, 3, 8, we_hi, we_lo, 5 * D, we_hi, we_lo, 5 * D,
            noadd, noscat, 0, 0, 0, Vs, nullptr, nullptr, nullptr);
    }
    cudaEventRecord(evs[1], s1);
    {   // V0t = hv0 @ Wv[256:512]
        Srcs s = {};
        s.Ahi[0] = hv0_hi; s.Alo[0] = hv0_lo; s.wblk[0] = 1;
        k_mma<<<dim3(2, N_ATOMS / 128), 256, SMEM_BYTES, s1>>>(
            s, D, 3, 8, wv_hi, wv_lo, 4 * D, wv_hi, wv_lo, 4 * D,
            noadd, noscat, 0, 0, 0, V0t, nullptr, nullptr, nullptr);
    }
    cudaEventRecord(evs[2], s1);

    // main: hu0, U0+Ue, Uv, Vd(0)
    {   // h_u0 = tanh(mol_mean @ W_fu)
        Srcs s = {};
        s.Ahi[0] = mm_hi; s.Alo[0] = mm_lo; s.wblk[0] = 0;
        k_mma<<<dim3(2, N_MOLS / 128), 256, SMEM_BYTES>>>(
            s, D_IN, 2, 4, wfu_hi, wfu_lo, D_IN, wfu_hi, wfu_lo, D_IN,
            noadd, noscat, 1, 0, 0, nullptr, nullptr, hu0_hi, hu0_lo);
    }
    {   // merged: U0 | Ue(0)
        Srcs s = {};
        s.Ahi[0] = hu0_hi; s.Alo[0] = hu0_lo; s.wblk[0] = 1;
        k_mma<<<dim3(2, 2 * N_MOLS / 128), 256, SMEM_BYTES>>>(
            s, D, 3, 8, wu_hi, wu_lo, 4 * D, we_hi, we_lo, 5 * D,
            noadd, noscat, 0, N_MOLS / 128, 4, U0, Ue, nullptr, nullptr);
    }
    {   // Uv(0)
        Srcs s = {};
        s.Ahi[0] = hu0_hi; s.Alo[0] = hu0_lo; s.wblk[0] = 3;
        k_mma<<<dim3(2, N_MOLS / 128), 256, SMEM_BYTES>>>(
            s, D, 3, 8, wv_hi, wv_lo, 4 * D, wv_hi, wv_lo, 4 * D,
            noadd, noscat, 0, 0, 0, Uv, nullptr, nullptr, nullptr);
    }
    {   // Vd(0)
        Srcs s = {};
        s.Ahi[0] = hv0_hi; s.Alo[0] = hv0_lo; s.wblk[0] = 3;
        k_mma<<<dim3(2, N_ATOMS / 128), 256, SMEM_BYTES>>>(
            s, D, 3, 8, we_hi, we_lo, 5 * D, we_hi, we_lo, 5 * D,
            noadd, noscat, 0, 0, 0, Vd, nullptr, nullptr, nullptr);
    }

    const bf16 *cur_he_hi = he0_hi, *cur_he_lo = he0_lo;
    const bf16 *cur_hv_hi = hv0_hi, *cur_hv_lo = hv0_lo;
    const bf16 *cur_hu_hi = hu0_hi, *cur_hu_lo = hu0_lo;

    cudaStreamWaitEvent(0, evs[1], 0);

    int evi = 3;
    int hebuf = 0, hvbuf = 0, hubuf = 0;
    for (int it = 0; it < 3; it++) {
        // edge update (fused gathers + scatter)
        {
            Srcs s = {};
            s.Ahi[0] = cur_he_hi;  s.Alo[0] = cur_he_lo;  s.wblk[0] = 0;
            Adds a = {};
            a.direct = E0;
            a.gat[0] = Ue; a.gidx[0] = bond_mol;
            a.gat[1] = Vs; a.gidx[1] = bond_src;
            a.gat[2] = Vd; a.gidx[2] = bond_dst;
            if (it == 2) {
                k_mma<<<dim3(2, N_BONDS / 128), 256, SMEM_BYTES>>>(
                    s, D, 3, 8, we_hi, we_lo, 5 * D, we_hi, we_lo, 5 * D,
                    a, noscat, 2, 0, 0, (float*)d_out, nullptr, nullptr, nullptr);
                break;
            }
            Scat sc = {ebv_f, bond_src, bond_dst};
            bf16* nh = he_hi + (size_t)hebuf * SZ_E;
            bf16* nl = he_lo + (size_t)hebuf * SZ_E;
            k_mma<<<dim3(2, N_BONDS / 128), 256, SMEM_BYTES>>>(
                s, D, 3, 8, we_hi, we_lo, 5 * D, we_hi, we_lo, 5 * D,
                a, sc, 1, 0, 0, nullptr, nullptr, nh, nl);
            cur_he_hi = nh; cur_he_lo = nl;
            hebuf ^= 1;
        }

        // fork: he-segsum on s1
        cudaEventRecord(evs[evi], 0);
        cudaStreamWaitEvent(s1, evs[evi], 0);
        k_segsum<<<N_MOLS, 128, 0, s1>>>(cur_he_hi, cur_he_lo, boff, ebar_hi, ebar_lo);
        cudaEventRecord(evs[evi + 1], s1);

        // node update (it==0 needs V0t)
        if (it == 0) cudaStreamWaitEvent(0, evs[2], 0);
        {
            Srcs s = {};
            s.Ahi[0] = cur_hv_hi;  s.Alo[0] = cur_hv_lo;  s.wblk[0] = 0;
            s.Ahi[1] = ebv_f;  s.wblk[1] = 2;  s.isf32[1] = 1;
            Adds a = {};
            a.direct = V0t;
            a.gat[0] = Uv; a.gidx[0] = atom_mol;
            bf16* nh = hv_hi + (size_t)hvbuf * SZ_V;
            bf16* nl = hv_lo + (size_t)hvbuf * SZ_V;
            k_mma<<<dim3(2, N_ATOMS / 128), 256, SMEM_BYTES>>>(
                s, D, 3, 16, wv_hi, wv_lo, 4 * D, wv_hi, wv_lo, 4 * D,
                a, noscat, 1, 0, 0, nullptr, nullptr, nh, nl);
            cur_hv_hi = nh; cur_hv_lo = nl;
            hvbuf ^= 1;
        }

        // fork: ebv clear + Vs(it+1) on s1 (ordered after node GEMM)
        cudaEventRecord(evs[evi + 2], 0);
        cudaStreamWaitEvent(s1, evs[evi + 2], 0);
        if (it == 0)
            cudaMemsetAsync(ebv_f, 0, SZ_V * sizeof(float), s1);
        {
            Srcs s = {};
            s.Ahi[0] = cur_hv_hi;  s.Alo[0] = cur_hv_lo;  s.wblk[0] = 2;
            k_mma<<<dim3(2, N_ATOMS / 128), 256, SMEM_BYTES, s1>>>(
                s, D, 3, 8, we_hi, we_lo, 5 * D, we_hi, we_lo, 5 * D,
                noadd, noscat, 0, 0, 0, Vs, nullptr, nullptr, nullptr);
        }
        cudaEventRecord(evs[evi + 3], s1);

        // main: hv-segsum, global, Ue(+Uv), Vd(it+1)
        k_segsum<<<N_MOLS, 128>>>(cur_hv_hi, cur_hv_lo, aoff, vbar_hi, vbar_lo);
        cudaStreamWaitEvent(0, evs[evi + 1], 0);
        {
            Srcs s = {};
            s.Ahi[0] = cur_hu_hi;  s.Alo[0] = cur_hu_lo;  s.wblk[0] = 0;
            s.Ahi[1] = ebar_hi;  s.Alo[1] = ebar_lo;  s.wblk[1] = 2;
            s.Ahi[2] = vbar_hi;  s.Alo[2] = vbar_lo;  s.wblk[2] = 3;
            Adds a = {};
            a.direct = U0;
            bf16* nh = hu_hi + (size_t)hubuf * SZ_U;
            bf16* nl = hu_lo + (size_t)hubuf * SZ_U;
            k_mma<<<dim3(2, N_MOLS / 128), 256, SMEM_BYTES>>>(
                s, D, 3, 24, wu_hi, wu_lo, 4 * D, wu_hi, wu_lo, 4 * D,
                a, noscat, 1, 0, 0, nullptr, nullptr, nh, nl);
            cur_hu_hi = nh; cur_hu_lo = nl;
            hubuf ^= 1;
        }
        {
            Srcs s = {};
            s.Ahi[0] = cur_hu_hi; s.Alo[0] = cur_hu_lo; s.wblk[0] = 4;
            if (it + 1 < 2) {
                k_mma<<<dim3(2, 2 * N_MOLS / 128), 256, SMEM_BYTES>>>(
                    s, D, 3, 8, we_hi, we_lo, 5 * D, wv_hi, wv_lo, 4 * D,
                    noadd, noscat, 0, N_MOLS / 128, 3, Ue, Uv, nullptr, nullptr);
            } else {
                k_mma<<<dim3(2, N_MOLS / 128), 256, SMEM_BYTES>>>(
                    s, D, 3, 8, we_hi, we_lo, 5 * D, we_hi, we_lo, 5 * D,
                    noadd, noscat, 0, 0, 0, Ue, nullptr, nullptr, nullptr);
            }
        }
        {   // Vd(it+1) on main
            Srcs s = {};
            s.Ahi[0] = cur_hv_hi;  s.Alo[0] = cur_hv_lo;  s.wblk[0] = 3;
            k_mma<<<dim3(2, N_ATOMS / 128), 256, SMEM_BYTES>>>(
                s, D, 3, 8, we_hi, we_lo, 5 * D, we_hi, we_lo, 5 * D,
                noadd, noscat, 0, 0, 0, Vd, nullptr, nullptr, nullptr);
        }
        // join s1 before next edge
        cudaStreamWaitEvent(0, evs[evi + 3], 0);
        evi += 4;
    }
}

// round 17
// speedup vs baseline: 1.0236x; 1.0057x over previous
#include <cuda_runtime.h>
#include <cuda_bf16.h>
#include <math.h>
#include <stdint.h>

typedef __nv_bfloat16 bf16;

#define N_ATOMS 65536
#define N_BONDS 98304
#define N_MOLS  4096
#define D_IN    128
#define D       256

// ---------------- scratch (device globals; no allocation allowed) ----------------
__device__ bf16 g_he_hi [2][(size_t)N_BONDS * D];
__device__ bf16 g_he_lo [2][(size_t)N_BONDS * D];
__device__ bf16 g_he0_hi[(size_t)N_BONDS * D];
__device__ bf16 g_he0_lo[(size_t)N_BONDS * D];
__device__ bf16 g_hv_hi [2][(size_t)N_ATOMS * D];
__device__ bf16 g_hv_lo [2][(size_t)N_ATOMS * D];
__device__ bf16 g_hv0_hi[(size_t)N_ATOMS * D];
__device__ bf16 g_hv0_lo[(size_t)N_ATOMS * D];
__device__ float g_ebv_f [(size_t)N_ATOMS * D];
__device__ bf16 g_hu_hi [2][(size_t)N_MOLS * D];
__device__ bf16 g_hu_lo [2][(size_t)N_MOLS * D];
__device__ bf16 g_hu0_hi[(size_t)N_MOLS * D];
__device__ bf16 g_hu0_lo[(size_t)N_MOLS * D];
__device__ bf16 g_ebar_hi[(size_t)N_MOLS * D];
__device__ bf16 g_ebar_lo[(size_t)N_MOLS * D];
__device__ bf16 g_vbar_hi[(size_t)N_MOLS * D];
__device__ bf16 g_vbar_lo[(size_t)N_MOLS * D];
__device__ float g_mm_f [(size_t)N_MOLS * D_IN];
__device__ bf16 g_we_hi [(size_t)D * 5 * D];
__device__ bf16 g_we_lo [(size_t)D * 5 * D];
__device__ bf16 g_wv_hi [(size_t)D * 4 * D];
__device__ bf16 g_wv_lo [(size_t)D * 4 * D];
__device__ bf16 g_wu_hi [(size_t)D * 4 * D];
__device__ bf16 g_wu_lo [(size_t)D * 4 * D];
__device__ bf16 g_wfv_hi[(size_t)D * D_IN];
__device__ bf16 g_wfv_lo[(size_t)D * D_IN];
__device__ bf16 g_wfu_hi[(size_t)D * D_IN];
__device__ bf16 g_wfu_lo[(size_t)D * D_IN];
// precomputed fp32 epilogue-add terms
__device__ float g_E0 [(size_t)N_BONDS * D];
__device__ float g_V0t[(size_t)N_ATOMS * D];
__device__ float g_U0 [(size_t)N_MOLS * D];
__device__ float g_Ue [(size_t)N_MOLS * D];
__device__ float g_Uv [(size_t)N_MOLS * D];
__device__ float g_Vs [(size_t)N_ATOMS * D];
__device__ float g_Vd [(size_t)N_ATOMS * D];
__device__ int  g_boff[N_MOLS + 1];
__device__ int  g_aoff[N_MOLS + 1];

// ---------------- helpers ----------------
__device__ __forceinline__ uint32_t smem_u32(const void* p) {
    uint32_t a;
    asm("{ .reg .u64 t; cvta.to.shared.u64 t, %1; cvt.u32.u64 %0, t; }" : "=r"(a) : "l"(p));
    return a;
}
__device__ __forceinline__ void cp16(uint32_t dst, const void* src) {
    asm volatile("cp.async.cg.shared.global [%0], [%1], 16;" :: "r"(dst), "l"(src) : "memory");
}
#define CP_COMMIT()  asm volatile("cp.async.commit_group;" ::: "memory")
#define CP_WAIT0()   asm volatile("cp.async.wait_group 0;" ::: "memory")

__device__ __forceinline__ void ldsm4(uint32_t* r, uint32_t addr) {
    asm volatile("ldmatrix.sync.aligned.m8n8.x4.shared.b16 {%0,%1,%2,%3}, [%4];"
        : "=r"(r[0]), "=r"(r[1]), "=r"(r[2]), "=r"(r[3]) : "r"(addr));
}
__device__ __forceinline__ void mma_bf16(float* c, const uint32_t* a, const uint32_t* b) {
    asm volatile(
        "mma.sync.aligned.m16n8k16.row.col.f32.bf16.bf16.f32 "
        "{%0,%1,%2,%3}, {%4,%5,%6,%7}, {%8,%9}, {%0,%1,%2,%3};"
        : "+f"(c[0]), "+f"(c[1]), "+f"(c[2]), "+f"(c[3])
        : "r"(a[0]), "r"(a[1]), "r"(a[2]), "r"(a[3]), "r"(b[0]), "r"(b[1]));
}
__device__ __forceinline__ void red2(float* p, float a, float b) {
    asm volatile("red.global.add.v2.f32 [%0], {%1,%2};"
        :: "l"(p), "f"(a), "f"(b) : "memory");
}
__device__ __forceinline__ void split1(float v, bf16& h, bf16& l) {
    h = __float2bfloat16(v);
    l = __float2bfloat16(v - __bfloat162float(h));
}
// packed split: 2 cvt + shl/and + 2 sub per PAIR of values
__device__ __forceinline__ void split2(float v0, float v1, uint32_t& h2, uint32_t& l2) {
    asm("cvt.rn.bf16x2.f32 %0, %1, %2;" : "=r"(h2) : "f"(v1), "f"(v0));
    const float f0 = __uint_as_float(h2 << 16);
    const float f1 = __uint_as_float(h2 & 0xffff0000u);
    const float l0 = v0 - f0;
    const float l1 = v1 - f1;
    asm("cvt.rn.bf16x2.f32 %0, %1, %2;" : "=r"(l2) : "f"(l1), "f"(l0));
}
__device__ __forceinline__ float tanh_approx(float x) {
    float y;
    asm("tanh.approx.f32 %0, %1;" : "=f"(y) : "f"(x));
    return y;
}
__device__ __forceinline__ float tanh_precise(float x) {
    const float e = __expf(2.0f * x);
    return 1.0f - __fdividef(2.0f, e + 1.0f);
}

// ---------------- fused multi-source bf16x3 GEMM (+adds, +scatter, +tanh) ---------
struct Srcs {
    const void* Ahi[4];
    const void* Alo[4];
    const int*  idx[4];
    int         wblk[4];
    int         isf32[4];
};
struct Adds {
    const float* direct;
    const float* gat[3];
    const int*   gidx[3];
};
struct Scat {
    float*     buf;
    const int* i0;
    const int* i1;
};

#define TILE_B   10240
#define SM_A     0
#define SM_B     40960
#define SMEM_BYTES 81920

__global__ void __launch_bounds__(256, 2)
k_mma(Srcs srcs, int ksrc, int cshift, int n_chunks,
      const bf16* __restrict__ Whi, const bf16* __restrict__ Wlo, int kstride,
      const bf16* __restrict__ Whi2, const bf16* __restrict__ Wlo2, int kstride2,
      Adds adds, Scat scat, int do_tanh,
      int ysplit, int wblk_alt,
      float* __restrict__ out_f32, float* __restrict__ out_alt,
      bf16* __restrict__ out_hi, bf16* __restrict__ out_lo)
{
    extern __shared__ char smc[];
    const uint32_t smu = smem_u32(smc);

    const int tid  = threadIdx.x;
    const int lane = tid & 31;
    const int w    = tid >> 5;
    const int wm   = w & 3;
    const int wn   = w >> 2;
    const int lr   = lane >> 2;
    const int lc   = lane & 3;

    const int n0 = blockIdx.x * 128;
    const int yb = blockIdx.y;
    const bool alt = (ysplit > 0) && (yb >= ysplit);
    const int m0 = (alt ? yb - ysplit : yb) * 128;

    const int cmask = (ksrc >> 5) - 1;

    const int r8 = lane & 7, j8 = lane >> 3;
    const uint32_t offA = (uint32_t)((r8 + (j8 & 1) * 8) * 80 + ((j8 >> 1) & 1) * 16)
                        + (uint32_t)(wm * 32) * 80u;
    const uint32_t offB = (uint32_t)(r8 * 80 + ((j8 >> 1) & 1) * 640 + (j8 & 1) * 16)
                        + (uint32_t)(wn * 64) * 80u;

    const int arow = tid >> 1;
    const int apl  = tid & 1;
    int cur_s = -1, is32 = 0, wcur = 0;
    const bf16*  aptr = nullptr;
    const float* a32  = nullptr;
    const bf16* wbase = alt ? (apl ? Wlo2 : Whi2) : (apl ? Wlo : Whi);
    const int   kstr  = alt ? kstride2 : kstride;

    auto load_chunk = [&](int c) {
        const int buf = c & 1;
        const int s = c >> cshift;
        if (s != cur_s) {
            cur_s = s;
            is32 = srcs.isf32[s];
            int gr = m0 + arow;
            const int* ix = srcs.idx[s];
            if (ix) gr = __ldg(ix + gr);
            if (is32) a32 = (const float*)srcs.Ahi[s] + (size_t)gr * ksrc;
            else aptr = (const bf16*)(apl ? srcs.Alo[s] : srcs.Ahi[s]) + (size_t)gr * ksrc;
            wcur = (s == 0 && alt) ? wblk_alt : srcs.wblk[s];
        }
        const uint32_t ad = smu + (uint32_t)(SM_A + apl * 2 * TILE_B + buf * TILE_B + arow * 80);
        if (is32) {
            const float* fs = a32 + ((c & cmask) << 5);
#pragma unroll
            for (int i = 0; i < 4; i++) {
                float4 x = __ldg((const float4*)(fs + i * 8));
                float4 y = __ldg((const float4*)(fs + i * 8 + 4));
                uint32_t h, l, r0, r1, r2, r3;
                split2(x.x, x.y, h, l); r0 = apl ? l : h;
                split2(x.z, x.w, h, l); r1 = apl ? l : h;
                split2(y.x, y.y, h, l); r2 = apl ? l : h;
                split2(y.z, y.w, h, l); r3 = apl ? l : h;
                asm volatile("st.shared.v4.b32 [%0], {%1,%2,%3,%4};"
                    :: "r"(ad + (uint32_t)(i * 16)), "r"(r0), "r"(r1), "r"(r2), "r"(r3)
                    : "memory");
            }
        } else {
            const bf16* as = aptr + ((c & cmask) << 5);
            cp16(ad,      as);
            cp16(ad + 16, as + 8);
            cp16(ad + 32, as + 16);
            cp16(ad + 48, as + 24);
        }
        const bf16* bs = wbase + (size_t)(n0 + arow) * kstr
                       + (wcur << 8) + ((c & cmask) << 5);
        const uint32_t bd = smu + (uint32_t)(SM_B + apl * 2 * TILE_B + buf * TILE_B + arow * 80);
        cp16(bd,      bs);
        cp16(bd + 16, bs + 8);
        cp16(bd + 32, bs + 16);
        cp16(bd + 48, bs + 24);
    };

    float acc[2][8][4];
#pragma unroll
    for (int mi = 0; mi < 2; mi++)
#pragma unroll
        for (int nj = 0; nj < 8; nj++)
#pragma unroll
            for (int q = 0; q < 4; q++) acc[mi][nj][q] = 0.f;

    load_chunk(0);
    CP_COMMIT();

    for (int c = 0; c < n_chunks; c++) {
        CP_WAIT0();
        __syncthreads();
        if (c + 1 < n_chunks) load_chunk(c + 1);
        CP_COMMIT();

        const int buf = c & 1;
        const uint32_t aH = smu + SM_A + (uint32_t)(buf * TILE_B);
        const uint32_t aL = aH + 2u * TILE_B;
        const uint32_t bH = smu + SM_B + (uint32_t)(buf * TILE_B);
        const uint32_t bL = bH + 2u * TILE_B;

#pragma unroll
        for (int ks = 0; ks < 2; ks++) {
            const uint32_t kb = (uint32_t)(ks * 32);
            uint32_t ah[2][4], al[2][4];
            ldsm4(ah[0], aH + offA + kb);
            ldsm4(ah[1], aH + offA + 1280u + kb);
            ldsm4(al[0], aL + offA + kb);
            ldsm4(al[1], aL + offA + 1280u + kb);
#pragma unroll
            for (int g = 0; g < 2; g++) {
                const uint32_t go = (uint32_t)(g * 2560);
                uint32_t bh[4][2], bl[4][2];
                ldsm4(&bh[0][0], bH + offB + go + kb);
                ldsm4(&bh[2][0], bH + offB + go + 1280u + kb);
                ldsm4(&bl[0][0], bL + offB + go + kb);
                ldsm4(&bl[2][0], bL + offB + go + 1280u + kb);
#pragma unroll
                for (int mi = 0; mi < 2; mi++)
#pragma unroll
                    for (int q = 0; q < 4; q++) {
                        float* acq = acc[mi][g * 4 + q];
                        mma_bf16(acq, ah[mi], bh[q]);
                        mma_bf16(acq, ah[mi], bl[q]);
                        mma_bf16(acq, al[mi], bh[q]);
                    }
            }
        }
        __syncthreads();
    }

    float* outf = alt ? out_alt : out_f32;

    // epilogue
#pragma unroll
    for (int mi = 0; mi < 2; mi++) {
        const int r0 = m0 + wm * 32 + mi * 16 + lr;
        const int r1 = r0 + 8;
        const float* dp0 = adds.direct ? adds.direct + (size_t)r0 * D : nullptr;
        const float* dp1 = adds.direct ? adds.direct + (size_t)r1 * D : nullptr;
        const float* gp[3][2];
#pragma unroll
        for (int t = 0; t < 3; t++) {
            if (adds.gat[t]) {
                gp[t][0] = adds.gat[t] + (size_t)__ldg(adds.gidx[t] + r0) * D;
                gp[t][1] = adds.gat[t] + (size_t)__ldg(adds.gidx[t] + r1) * D;
            } else {
                gp[t][0] = nullptr; gp[t][1] = nullptr;
            }
        }
        float *s00 = nullptr, *s01 = nullptr, *s10 = nullptr, *s11 = nullptr;
        if (scat.buf) {
            s00 = scat.buf + (size_t)__ldg(scat.i0 + r0) * D;
            s01 = scat.buf + (size_t)__ldg(scat.i0 + r1) * D;
            s10 = scat.buf + (size_t)__ldg(scat.i1 + r0) * D;
            s11 = scat.buf + (size_t)__ldg(scat.i1 + r1) * D;
        }
#pragma unroll
        for (int nj = 0; nj < 8; nj++) {
            const int col = n0 + wn * 64 + nj * 8 + lc * 2;
            float v0 = acc[mi][nj][0];
            float v1 = acc[mi][nj][1];
            float v2 = acc[mi][nj][2];
            float v3 = acc[mi][nj][3];
            if (dp0) {
                float2 t0 = *(const float2*)(dp0 + col);
                float2 t1 = *(const float2*)(dp1 + col);
                v0 += t0.x; v1 += t0.y; v2 += t1.x; v3 += t1.y;
            }
#pragma unroll
            for (int t = 0; t < 3; t++) {
                if (gp[t][0]) {
                    float2 t0 = *(const float2*)(gp[t][0] + col);
                    float2 t1 = *(const float2*)(gp[t][1] + col);
                    v0 += t0.x; v1 += t0.y; v2 += t1.x; v3 += t1.y;
                }
            }
            if (do_tanh == 1) {
                v0 = tanh_approx(v0); v1 = tanh_approx(v1);
                v2 = tanh_approx(v2); v3 = tanh_approx(v3);
            } else if (do_tanh == 2) {
                v0 = tanh_precise(v0); v1 = tanh_precise(v1);
                v2 = tanh_precise(v2); v3 = tanh_precise(v3);
            }
            if (s00) {
                red2(s00 + col, v0, v1);
                red2(s10 + col, v0, v1);
                red2(s01 + col, v2, v3);
                red2(s11 + col, v2, v3);
            }
            if (outf) {
                *(float2*)(outf + (size_t)r0 * D + col) = make_float2(v0, v1);
                *(float2*)(outf + (size_t)r1 * D + col) = make_float2(v2, v3);
            }
            if (out_hi) {
                uint32_t h01, l01, h23, l23;
                split2(v0, v1, h01, l01);
                split2(v2, v3, h23, l23);
                const size_t o0 = (size_t)r0 * D + col;
                const size_t o1 = (size_t)r1 * D + col;
                *(uint32_t*)(out_hi + o0) = h01;  *(uint32_t*)(out_lo + o0) = l01;
                *(uint32_t*)(out_hi + o1) = h23;  *(uint32_t*)(out_lo + o1) = l23;
            }
        }
    }
}

// ---------------- small kernels ----------------
__global__ void k_offsets2(const int* __restrict__ bids, const int* __restrict__ aids,
                           int* __restrict__ boff, int* __restrict__ aoff)
{
    int m = blockIdx.x * blockDim.x + threadIdx.x;
    if (m > N_MOLS) return;
    const int* ids = blockIdx.y ? aids : bids;
    const int n    = blockIdx.y ? N_ATOMS : N_BONDS;
    int* off       = blockIdx.y ? aoff : boff;
    int lo = 0, hi = n;
    while (lo < hi) {
        int mid = (lo + hi) >> 1;
        if (ids[mid] < m) lo = mid + 1; else hi = mid;
    }
    off[m] = lo;
}

// writes fp32 mol-mean (consumed via the GEMM fp32-source path)
__global__ void k_mol_mean(const float* __restrict__ atoms,
                           const int* __restrict__ aoff,
                           float* __restrict__ mm)
{
    const int m = blockIdx.x, d = threadIdx.x;
    const int s = aoff[m], e = aoff[m + 1];
    float acc = 0.f;
    for (int i = s; i < e; i++) acc += atoms[(size_t)i * D_IN + d];
    float cnt = (float)(e - s);
    if (cnt < 1.f) cnt = 1.f;
    mm[(size_t)m * D_IN + d] = acc / cnt;
}

__global__ void k_init_he0(const float* __restrict__ bo,
                           const float* __restrict__ Wfe,
                           bf16* __restrict__ e0hi, bf16* __restrict__ e0lo)
{
    const int b = blockIdx.x * 2 + (threadIdx.x >> 7);
    const int d = (threadIdx.x & 127) * 2;
    const float o = __ldg(bo + b);
    const float2 wf = __ldg((const float2*)(Wfe + d));
    uint32_t h2, l2;
    split2(tanh_approx(o * wf.x), tanh_approx(o * wf.y), h2, l2);
    const size_t off = (size_t)b * D + d;
    *(uint32_t*)(e0hi + off) = h2;
    *(uint32_t*)(e0lo + off) = l2;
}

// 128 threads, 2 cols per thread, packed loads/stores
__global__ void k_segsum(const bf16* __restrict__ xhi, const bf16* __restrict__ xlo,
                         const int* __restrict__ off,
                         bf16* __restrict__ ohi, bf16* __restrict__ olo)
{
    const int m = blockIdx.x, d2 = threadIdx.x;
    const int s = off[m], e = off[m + 1];
    float a0 = 0.f, a1 = 0.f;
    for (int i = s; i < e; i++) {
        const size_t o = (size_t)i * D + d2 * 2;
        const float2 h = __bfloat1622float2(*(const __nv_bfloat162*)(xhi + o));
        const float2 l = __bfloat1622float2(*(const __nv_bfloat162*)(xlo + o));
        a0 += h.x + l.x;
        a1 += h.y + l.y;
    }
    uint32_t h2, l2;
    split2(a0, a1, h2, l2);
    ((uint32_t*)(ohi + (size_t)m * D))[d2] = h2;
    ((uint32_t*)(olo + (size_t)m * D))[d2] = l2;
}

struct TransJob { const float* W; bf16* hi; bf16* lo; int K; };
struct TransJobs { TransJob j[5]; };

__global__ void k_transpose_all(TransJobs jobs)
{
    __shared__ float t[32][33];
    const TransJob job = jobs.j[blockIdx.z];
    const int k0 = blockIdx.x * 32;
    if (k0 >= job.K) return;
    const int nb = blockIdx.y * 32;
    const int tx = threadIdx.x, ty = threadIdx.y;
#pragma unroll
    for (int i = 0; i < 4; i++)
        t[ty + 8 * i][tx] = job.W[(size_t)(k0 + ty + 8 * i) * D + nb + tx];
    __syncthreads();
#pragma unroll
    for (int i = 0; i < 4; i++) {
        bf16 h, l;
        split1(t[tx][ty + 8 * i], h, l);
        const size_t o = (size_t)(nb + ty + 8 * i) * job.K + k0 + tx;
        job.hi[o] = h;
        job.lo[o] = l;
    }
}

// ---------------- host orchestration ----------------
static bf16* sym_bf16(const void* sym) {
    void* p = nullptr;
    cudaGetSymbolAddress(&p, sym);
    return (bf16*)p;
}
static float* sym_f32(const void* sym) {
    void* p = nullptr;
    cudaGetSymbolAddress(&p, sym);
    return (float*)p;
}

extern "C" void kernel_launch(void* const* d_in, const int* in_sizes, int n_in,
                              void* d_out, int out_size)
{
    const float* atoms       = (const float*)d_in[0];
    const float* bond_orders = (const float*)d_in[1];
    const int*   bond_src    = (const int*)  d_in[2];
    const int*   bond_dst    = (const int*)  d_in[3];
    const int*   atom_mol    = (const int*)  d_in[4];
    const int*   bond_mol    = (const int*)  d_in[5];
    const float* W_fe        = (const float*)d_in[6];
    const float* W_fv        = (const float*)d_in[7];
    const float* W_fu        = (const float*)d_in[8];
    const float* W_e         = (const float*)d_in[9];
    const float* W_v         = (const float*)d_in[10];
    const float* W_u         = (const float*)d_in[11];

    bf16* he_hi  = sym_bf16(g_he_hi);   bf16* he_lo  = sym_bf16(g_he_lo);
    bf16* he0_hi = sym_bf16(g_he0_hi);  bf16* he0_lo = sym_bf16(g_he0_lo);
    bf16* hv_hi  = sym_bf16(g_hv_hi);   bf16* hv_lo  = sym_bf16(g_hv_lo);
    bf16* hv0_hi = sym_bf16(g_hv0_hi);  bf16* hv0_lo = sym_bf16(g_hv0_lo);
    bf16* hu_hi  = sym_bf16(g_hu_hi);   bf16* hu_lo  = sym_bf16(g_hu_lo);
    bf16* hu0_hi = sym_bf16(g_hu0_hi);  bf16* hu0_lo = sym_bf16(g_hu0_lo);
    bf16* ebar_hi= sym_bf16(g_ebar_hi); bf16* ebar_lo= sym_bf16(g_ebar_lo);
    bf16* vbar_hi= sym_bf16(g_vbar_hi); bf16* vbar_lo= sym_bf16(g_vbar_lo);
    float* mm_f  = sym_f32(g_mm_f);
    bf16* we_hi  = sym_bf16(g_we_hi);   bf16* we_lo  = sym_bf16(g_we_lo);
    bf16* wv_hi  = sym_bf16(g_wv_hi);   bf16* wv_lo  = sym_bf16(g_wv_lo);
    bf16* wu_hi  = sym_bf16(g_wu_hi);   bf16* wu_lo  = sym_bf16(g_wu_lo);
    bf16* wfv_hi = sym_bf16(g_wfv_hi);  bf16* wfv_lo = sym_bf16(g_wfv_lo);
    bf16* wfu_hi = sym_bf16(g_wfu_hi);  bf16* wfu_lo = sym_bf16(g_wfu_lo);
    float* ebv_f = sym_f32(g_ebv_f);
    float* E0    = sym_f32(g_E0);
    float* V0t   = sym_f32(g_V0t);
    float* U0    = sym_f32(g_U0);
    float* Ue    = sym_f32(g_Ue);
    float* Uv    = sym_f32(g_Uv);
    float* Vs    = sym_f32(g_Vs);
    float* Vd    = sym_f32(g_Vd);
    int *boff, *aoff;
    { void* p; cudaGetSymbolAddress(&p, g_boff); boff = (int*)p; }
    { void* p; cudaGetSymbolAddress(&p, g_aoff); aoff = (int*)p; }

    const size_t SZ_E = (size_t)N_BONDS * D;
    const size_t SZ_V = (size_t)N_ATOMS * D;
    const size_t SZ_U = (size_t)N_MOLS * D;

    cudaFuncSetAttribute(k_mma, cudaFuncAttributeMaxDynamicSharedMemorySize, SMEM_BYTES);

    static cudaStream_t s1 = nullptr;
    static cudaEvent_t evs[16];
    if (!s1) {
        cudaStreamCreateWithFlags(&s1, cudaStreamNonBlocking);
        for (int i = 0; i < 16; i++) cudaEventCreateWithFlags(&evs[i], cudaEventDisableTiming);
    }

    const Adds noadd = {};
    const Scat noscat = {};

    const int offBlocks = (N_MOLS + 1 + 255) / 256;
    k_offsets2<<<dim3(offBlocks, 2), 256>>>(bond_mol, atom_mol, boff, aoff);
    {
        TransJobs tj;
        tj.j[0] = {W_e,  we_hi,  we_lo,  5 * D};
        tj.j[1] = {W_v,  wv_hi,  wv_lo,  4 * D};
        tj.j[2] = {W_u,  wu_hi,  wu_lo,  4 * D};
        tj.j[3] = {W_fv, wfv_hi, wfv_lo, D_IN};
        tj.j[4] = {W_fu, wfu_hi, wfu_lo, D_IN};
        k_transpose_all<<<dim3(5 * D / 32, 8, 5), dim3(32, 8)>>>(tj);
    }
    {   // h_v0 = tanh(atoms @ W_fv)  — reads raw fp32 atoms (no f2p pass)
        Srcs s = {};
        s.Ahi[0] = atoms; s.wblk[0] = 0; s.isf32[0] = 1;
        k_mma<<<dim3(2, N_ATOMS / 128), 256, SMEM_BYTES>>>(
            s, D_IN, 2, 4, wfv_hi, wfv_lo, D_IN, wfv_hi, wfv_lo, D_IN,
            noadd, noscat, 1, 0, 0, nullptr, nullptr, hv0_hi, hv0_lo);
    }
    k_init_he0<<<N_BONDS / 2, 256>>>(bond_orders, W_fe, he0_hi, he0_lo);
    k_mol_mean<<<N_MOLS, 128>>>(atoms, aoff, mm_f);
    cudaMemsetAsync(ebv_f, 0, SZ_V * sizeof(float), 0);

    // fork s1: E0 -> Vs(0) -> V0t
    cudaEventRecord(evs[0], 0);
    cudaStreamWaitEvent(s1, evs[0], 0);
    {   // E0 = he0 @ We[256:512]
        Srcs s = {};
        s.Ahi[0] = he0_hi; s.Alo[0] = he0_lo; s.wblk[0] = 1;
        k_mma<<<dim3(2, N_BONDS / 128), 256, SMEM_BYTES, s1>>>(
            s, D, 3, 8, we_hi, we_lo, 5 * D, we_hi, we_lo, 5 * D,
            noadd, noscat, 0, 0, 0, E0, nullptr, nullptr, nullptr);
    }
    {   // Vs(0) = hv0 @ We[512:768]
        Srcs s = {};
        s.Ahi[0] = hv0_hi; s.Alo[0] = hv0_lo; s.wblk[0] = 2;
        k_mma<<<dim3(2, N_ATOMS / 128), 256, SMEM_BYTES, s1>>>(
            s, D, 3, 8, we_hi, we_lo, 5 * D, we_hi, we_lo, 5 * D,
            noadd, noscat, 0, 0, 0, Vs, nullptr, nullptr, nullptr);
    }
    cudaEventRecord(evs[1], s1);
    {   // V0t = hv0 @ Wv[256:512]
        Srcs s = {};
        s.Ahi[0] = hv0_hi; s.Alo[0] = hv0_lo; s.wblk[0] = 1;
        k_mma<<<dim3(2, N_ATOMS / 128), 256, SMEM_BYTES, s1>>>(
            s, D, 3, 8, wv_hi, wv_lo, 4 * D, wv_hi, wv_lo, 4 * D,
            noadd, noscat, 0, 0, 0, V0t, nullptr, nullptr, nullptr);
    }
    cudaEventRecord(evs[2], s1);

    // main: hu0, U0+Ue, Uv, Vd(0)
    {   // h_u0 = tanh(mol_mean @ W_fu)  — reads fp32 mm
        Srcs s = {};
        s.Ahi[0] = mm_f; s.wblk[0] = 0; s.isf32[0] = 1;
        k_mma<<<dim3(2, N_MOLS / 128), 256, SMEM_BYTES>>>(
            s, D_IN, 2, 4, wfu_hi, wfu_lo, D_IN, wfu_hi, wfu_lo, D_IN,
            noadd, noscat, 1, 0, 0, nullptr, nullptr, hu0_hi, hu0_lo);
    }
    {   // merged: U0 | Ue(0)
        Srcs s = {};
        s.Ahi[0] = hu0_hi; s.Alo[0] = hu0_lo; s.wblk[0] = 1;
        k_mma<<<dim3(2, 2 * N_MOLS / 128), 256, SMEM_BYTES>>>(
            s, D, 3, 8, wu_hi, wu_lo, 4 * D, we_hi, we_lo, 5 * D,
            noadd, noscat, 0, N_MOLS / 128, 4, U0, Ue, nullptr, nullptr);
    }
    {   // Uv(0)
        Srcs s = {};
        s.Ahi[0] = hu0_hi; s.Alo[0] = hu0_lo; s.wblk[0] = 3;
        k_mma<<<dim3(2, N_MOLS / 128), 256, SMEM_BYTES>>>(
            s, D, 3, 8, wv_hi, wv_lo, 4 * D, wv_hi, wv_lo, 4 * D,
            noadd, noscat, 0, 0, 0, Uv, nullptr, nullptr, nullptr);
    }
    {   // Vd(0)
        Srcs s = {};
        s.Ahi[0] = hv0_hi; s.Alo[0] = hv0_lo; s.wblk[0] = 3;
        k_mma<<<dim3(2, N_ATOMS / 128), 256, SMEM_BYTES>>>(
            s, D, 3, 8, we_hi, we_lo, 5 * D, we_hi, we_lo, 5 * D,
            noadd, noscat, 0, 0, 0, Vd, nullptr, nullptr, nullptr);
    }

    const bf16 *cur_he_hi = he0_hi, *cur_he_lo = he0_lo;
    const bf16 *cur_hv_hi = hv0_hi, *cur_hv_lo = hv0_lo;
    const bf16 *cur_hu_hi = hu0_hi, *cur_hu_lo = hu0_lo;

    cudaStreamWaitEvent(0, evs[1], 0);

    int evi = 3;
    int hebuf = 0, hvbuf = 0, hubuf = 0;
    for (int it = 0; it < 3; it++) {
        // edge update (fused gathers + scatter)
        {
            Srcs s = {};
            s.Ahi[0] = cur_he_hi;  s.Alo[0] = cur_he_lo;  s.wblk[0] = 0;
            Adds a = {};
            a.direct = E0;
            a.gat[0] = Ue; a.gidx[0] = bond_mol;
            a.gat[1] = Vs; a.gidx[1] = bond_src;
            a.gat[2] = Vd; a.gidx[2] = bond_dst;
            if (it == 2) {
                k_mma<<<dim3(2, N_BONDS / 128), 256, SMEM_BYTES>>>(
                    s, D, 3, 8, we_hi, we_lo, 5 * D, we_hi, we_lo, 5 * D,
                    a, noscat, 2, 0, 0, (float*)d_out, nullptr, nullptr, nullptr);
                break;
            }
            Scat sc = {ebv_f, bond_src, bond_dst};
            bf16* nh = he_hi + (size_t)hebuf * SZ_E;
            bf16* nl = he_lo + (size_t)hebuf * SZ_E;
            k_mma<<<dim3(2, N_BONDS / 128), 256, SMEM_BYTES>>>(
                s, D, 3, 8, we_hi, we_lo, 5 * D, we_hi, we_lo, 5 * D,
                a, sc, 1, 0, 0, nullptr, nullptr, nh, nl);
            cur_he_hi = nh; cur_he_lo = nl;
            hebuf ^= 1;
        }

        // fork: he-segsum on s1
        cudaEventRecord(evs[evi], 0);
        cudaStreamWaitEvent(s1, evs[evi], 0);
        k_segsum<<<N_MOLS, 128, 0, s1>>>(cur_he_hi, cur_he_lo, boff, ebar_hi, ebar_lo);
        cudaEventRecord(evs[evi + 1], s1);

        // node update (it==0 needs V0t)
        if (it == 0) cudaStreamWaitEvent(0, evs[2], 0);
        {
            Srcs s = {};
            s.Ahi[0] = cur_hv_hi;  s.Alo[0] = cur_hv_lo;  s.wblk[0] = 0;
            s.Ahi[1] = ebv_f;  s.wblk[1] = 2;  s.isf32[1] = 1;
            Adds a = {};
            a.direct = V0t;
            a.gat[0] = Uv; a.gidx[0] = atom_mol;
            bf16* nh = hv_hi + (size_t)hvbuf * SZ_V;
            bf16* nl = hv_lo + (size_t)hvbuf * SZ_V;
            k_mma<<<dim3(2, N_ATOMS / 128), 256, SMEM_BYTES>>>(
                s, D, 3, 16, wv_hi, wv_lo, 4 * D, wv_hi, wv_lo, 4 * D,
                a, noscat, 1, 0, 0, nullptr, nullptr, nh, nl);
            cur_hv_hi = nh; cur_hv_lo = nl;
            hvbuf ^= 1;
        }

        // fork: ebv clear + Vs(it+1) on s1 (ordered after node GEMM)
        cudaEventRecord(evs[evi + 2], 0);
        cudaStreamWaitEvent(s1, evs[evi + 2], 0);
        if (it == 0)
            cudaMemsetAsync(ebv_f, 0, SZ_V * sizeof(float), s1);
        {
            Srcs s = {};
            s.Ahi[0] = cur_hv_hi;  s.Alo[0] = cur_hv_lo;  s.wblk[0] = 2;
            k_mma<<<dim3(2, N_ATOMS / 128), 256, SMEM_BYTES, s1>>>(
                s, D, 3, 8, we_hi, we_lo, 5 * D, we_hi, we_lo, 5 * D,
                noadd, noscat, 0, 0, 0, Vs, nullptr, nullptr, nullptr);
        }
        cudaEventRecord(evs[evi + 3], s1);

        // main: hv-segsum, global, Ue(+Uv), Vd(it+1)
        k_segsum<<<N_MOLS, 128>>>(cur_hv_hi, cur_hv_lo, aoff, vbar_hi, vbar_lo);
        cudaStreamWaitEvent(0, evs[evi + 1], 0);
        {
            Srcs s = {};
            s.Ahi[0] = cur_hu_hi;  s.Alo[0] = cur_hu_lo;  s.wblk[0] = 0;
            s.Ahi[1] = ebar_hi;  s.Alo[1] = ebar_lo;  s.wblk[1] = 2;
            s.Ahi[2] = vbar_hi;  s.Alo[2] = vbar_lo;  s.wblk[2] = 3;
            Adds a = {};
            a.direct = U0;
            bf16* nh = hu_hi + (size_t)hubuf * SZ_U;
            bf16* nl = hu_lo + (size_t)hubuf * SZ_U;
            k_mma<<<dim3(2, N_MOLS / 128), 256, SMEM_BYTES>>>(
                s, D, 3, 24, wu_hi, wu_lo, 4 * D, wu_hi, wu_lo, 4 * D,
                a, noscat, 1, 0, 0, nullptr, nullptr, nh, nl);
            cur_hu_hi = nh; cur_hu_lo = nl;
            hubuf ^= 1;
        }
        {
            Srcs s = {};
            s.Ahi[0] = cur_hu_hi; s.Alo[0] = cur_hu_lo; s.wblk[0] = 4;
            if (it + 1 < 2) {
                k_mma<<<dim3(2, 2 * N_MOLS / 128), 256, SMEM_BYTES>>>(
                    s, D, 3, 8, we_hi, we_lo, 5 * D, wv_hi, wv_lo, 4 * D,
                    noadd, noscat, 0, N_MOLS / 128, 3, Ue, Uv, nullptr, nullptr);
            } else {
                k_mma<<<dim3(2, N_MOLS / 128), 256, SMEM_BYTES>>>(
                    s, D, 3, 8, we_hi, we_lo, 5 * D, we_hi, we_lo, 5 * D,
                    noadd, noscat, 0, 0, 0, Ue, nullptr, nullptr, nullptr);
            }
        }
        {   // Vd(it+1) on main
            Srcs s = {};
            s.Ahi[0] = cur_hv_hi;  s.Alo[0] = cur_hv_lo;  s.wblk[0] = 3;
            k_mma<<<dim3(2, N_ATOMS / 128), 256, SMEM_BYTES>>>(
                s, D, 3, 8, we_hi, we_lo, 5 * D, we_hi, we_lo, 5 * D,
                noadd, noscat, 0, 0, 0, Vd, nullptr, nullptr, nullptr);
        }
        // join s1 before next edge
        cudaStreamWaitEvent(0, evs[evi + 3], 0);
        evi += 4;
    }
}